// round 9
// baseline (speedup 1.0000x reference)
#include <cuda_runtime.h>
#include <cuda_bf16.h>
#include <cstdint>

#define TS 47

// ---------------- fp32 scratch ----------------
__device__ __align__(128) float g_features[8192 * 256];
__device__ __align__(128) float g_featw1 [8192 * 512];
__device__ __align__(128) float g_embmx  [6016 * 1536];
__device__ __align__(128) float g_hidw2  [2 * 128 * 512];
__device__ __align__(128) float g_context[128 * 256];
__device__ __align__(128) float g_states [6016 * 512];

// ---------------- bf16 hi/lo pairs ----------------
__device__ __align__(128) __nv_bfloat16 g_wfc_hi [2048 * 256],  g_wfc_lo [2048 * 256];
__device__ __align__(128) __nv_bfloat16 g_feat_hi[8192 * 256],  g_feat_lo[8192 * 256];
__device__ __align__(128) __nv_bfloat16 g_w1_hi  [256 * 512],   g_w1_lo  [256 * 512];
__device__ __align__(128) __nv_bfloat16 g_etok_hi[6016 * 256],  g_etok_lo[6016 * 256];
__device__ __align__(128) __nv_bfloat16 g_gk2_hi [256 * 1536],  g_gk2_lo [256 * 1536];
__device__ __align__(128) __nv_bfloat16 g_st_hi  [6016 * 512],  g_st_lo  [6016 * 512];
__device__ __align__(128) __nv_bfloat16 g_f1w_hi [512 * 512],   g_f1w_lo [512 * 512];
__device__ __align__(128) __nv_bfloat16 g_f1o_hi [6016 * 512],  g_f1o_lo [6016 * 512];
__device__ __align__(128) __nv_bfloat16 g_f2w_hi [512 * 5000],  g_f2w_lo [512 * 5000];

// ---------------- barrier state (monotonic, replay-safe) ----------------
__device__ unsigned g_flags[128];
__device__ unsigned g_release;
__device__ unsigned g_epoch;

// ---------------- helpers ----------------
__device__ __forceinline__ float tanh_apx(float x) {
    float y;
    asm("tanh.approx.f32 %0, %1;" : "=f"(y) : "f"(x));
    return y;
}
__device__ __forceinline__ unsigned ld_acq(const unsigned* p) {
    unsigned v;
    asm volatile("ld.acquire.gpu.global.u32 %0, [%1];" : "=r"(v) : "l"(p));
    return v;
}
__device__ __forceinline__ void st_rel(unsigned* p, unsigned v) {
    asm volatile("st.release.gpu.global.u32 [%0], %1;" :: "l"(p), "r"(v) : "memory");
}
__device__ __forceinline__ void grid_bar2(int bid, int tid, unsigned tgt) {
    __syncthreads();
    if (bid == 0) {
        if (tid > 0 && tid < 128) {
            while ((int)(ld_acq(&g_flags[tid]) - tgt) < 0) { }
        }
        __syncthreads();
        if (tid == 0) st_rel(&g_release, tgt);
    } else {
        if (tid == 0) {
            st_rel(&g_flags[bid], tgt);
            while ((int)(ld_acq(&g_release) - tgt) < 0) { }
        }
        __syncthreads();
    }
}

__device__ __forceinline__ uint32_t smem_u32(const void* p) {
    uint32_t a;
    asm("{ .reg .u64 t; cvta.to.shared.u64 t, %1; cvt.u32.u64 %0, t; }"
        : "=r"(a) : "l"(p));
    return a;
}
__device__ __forceinline__ void ldsm_x4(uint32_t* r, uint32_t addr) {
    asm volatile("ldmatrix.sync.aligned.m8n8.x4.shared.b16 {%0,%1,%2,%3}, [%4];"
        : "=r"(r[0]), "=r"(r[1]), "=r"(r[2]), "=r"(r[3]) : "r"(addr));
}
__device__ __forceinline__ void ldsm_x2t(uint32_t* r, uint32_t addr) {
    asm volatile("ldmatrix.sync.aligned.m8n8.x2.trans.shared.b16 {%0,%1}, [%2];"
        : "=r"(r[0]), "=r"(r[1]) : "r"(addr));
}
__device__ __forceinline__ void mma_bf16(float* c, const uint32_t* a, const uint32_t* b) {
    asm volatile("mma.sync.aligned.m16n8k16.row.col.f32.bf16.bf16.f32 "
        "{%0,%1,%2,%3},{%4,%5,%6,%7},{%8,%9},{%0,%1,%2,%3};"
        : "+f"(c[0]), "+f"(c[1]), "+f"(c[2]), "+f"(c[3])
        : "r"(a[0]), "r"(a[1]), "r"(a[2]), "r"(a[3]), "r"(b[0]), "r"(b[1]));
}
__device__ __forceinline__ uint32_t packbf(__nv_bfloat16 a, __nv_bfloat16 b) {
    __nv_bfloat162 t = __halves2bfloat162(a, b);
    return *(uint32_t*)&t;
}
__device__ __forceinline__ void cpasync16(uint32_t sa, const void* ga, int sz) {
    asm volatile("cp.async.cg.shared.global [%0], [%1], 16, %2;"
                 :: "r"(sa), "l"(ga), "r"(sz) : "memory");
}

// ---------------- fp32 -> bf16 hi/lo convert ----------------
__global__ void cvt_pair(const float* __restrict__ s,
                         __nv_bfloat16* __restrict__ hi,
                         __nv_bfloat16* __restrict__ lo, int n)
{
    int i = (blockIdx.x * 256 + threadIdx.x) * 4;
    if (i >= n) return;
    float4 v = *(const float4*)(s + i);
    __nv_bfloat16 hx = __float2bfloat16(v.x), hy = __float2bfloat16(v.y);
    __nv_bfloat16 hz = __float2bfloat16(v.z), hw = __float2bfloat16(v.w);
    *(uint2*)(hi + i) = make_uint2(packbf(hx, hy), packbf(hz, hw));
    __nv_bfloat16 lx = __float2bfloat16(v.x - __bfloat162float(hx));
    __nv_bfloat16 ly = __float2bfloat16(v.y - __bfloat162float(hy));
    __nv_bfloat16 lz = __float2bfloat16(v.z - __bfloat162float(hz));
    __nv_bfloat16 lw = __float2bfloat16(v.w - __bfloat162float(hw));
    *(uint2*)(lo + i) = make_uint2(packbf(lx, ly), packbf(lz, lw));
}

// ---------------- bf16-pair tensor-core GEMM, cp.async double buffer ----------------
// AFP32: A supplied fp32 (split in-kernel); else preconverted hi/lo planes.
#define OFF_ALO 10240
#define OFF_BHI 20480
#define OFF_BLO 29184
#define STAGE   37888

template<bool AFP32>
__global__ void __launch_bounds__(256, 2) mma_gemm_bf(
    const float* __restrict__ Af32,
    const __nv_bfloat16* __restrict__ Ahi, const __nv_bfloat16* __restrict__ Alo,
    const __nv_bfloat16* __restrict__ Bhi, const __nv_bfloat16* __restrict__ Blo,
    const float* __restrict__ bias, float* __restrict__ C,
    __nv_bfloat16* __restrict__ Chi, __nv_bfloat16* __restrict__ Clo,
    int M, int N, int K, int relu, int remap)
{
    extern __shared__ char smem[];
    const int tid = threadIdx.x;
    const int wid = tid >> 5, lane = tid & 31;
    const int bm = blockIdx.y * 128, bn = blockIdx.x * 128;
    const int wm = (wid >> 2) * 64;
    const int wn = (wid & 3) * 32;
    const uint32_t sbase = smem_u32(smem);

    float acc[4][4][4] = {};
    const int nc = K >> 5;
    float4 va[4];

    auto issueB = [&](int k0, int s) {
        uint32_t sb = sbase + s * STAGE;
        #pragma unroll
        for (int i = 0; i < 2; i++) {
            int task = tid + (i << 8);
            int kk = task >> 4, n8 = (task & 15) << 3;
            int gc = bn + n8;
            uint32_t sa = sb + OFF_BHI + kk * 272 + (n8 << 1);
            size_t go = (size_t)(k0 + kk) * N + gc;
            int sz = (gc + 8 <= N) ? 16 : 0;
            cpasync16(sa, Bhi + go, sz);
            cpasync16(sa + (OFF_BLO - OFF_BHI), Blo + go, sz);
        }
    };
    auto issueA = [&](int k0, int s) {
        uint32_t sb = sbase + s * STAGE;
        #pragma unroll
        for (int i = 0; i < 2; i++) {
            int task = tid + (i << 8);
            int m = task >> 2, k8 = (task & 3) << 3;
            uint32_t sa = sb + m * 80 + (k8 << 1);
            size_t go = (size_t)(bm + m) * K + k0 + k8;
            cpasync16(sa, Ahi + go, 16);
            cpasync16(sa + OFF_ALO, Alo + go, 16);
        }
    };
    auto ldgA32 = [&](int k0) {
        #pragma unroll
        for (int i = 0; i < 4; i++) {
            int task = tid + (i << 8);
            int m = task >> 3, k4 = (task & 7) << 2;
            va[i] = *(const float4*)(Af32 + (size_t)(bm + m) * K + k0 + k4);
        }
    };
    auto cvtStoreA = [&](int s) {
        char* sD = smem + s * STAGE;
        #pragma unroll
        for (int i = 0; i < 4; i++) {
            int task = tid + (i << 8);
            int m = task >> 3, k4 = (task & 7) << 2;
            __nv_bfloat16 hx = __float2bfloat16(va[i].x);
            __nv_bfloat16 hy = __float2bfloat16(va[i].y);
            __nv_bfloat16 hz = __float2bfloat16(va[i].z);
            __nv_bfloat16 hw = __float2bfloat16(va[i].w);
            __nv_bfloat16 lx = __float2bfloat16(va[i].x - __bfloat162float(hx));
            __nv_bfloat16 ly = __float2bfloat16(va[i].y - __bfloat162float(hy));
            __nv_bfloat16 lz = __float2bfloat16(va[i].z - __bfloat162float(hz));
            __nv_bfloat16 lw = __float2bfloat16(va[i].w - __bfloat162float(hw));
            *(uint2*)(sD + m * 80 + (k4 << 1)) = make_uint2(packbf(hx, hy), packbf(hz, hw));
            *(uint2*)(sD + OFF_ALO + m * 80 + (k4 << 1)) = make_uint2(packbf(lx, ly), packbf(lz, lw));
        }
    };

    if (AFP32) {
        ldgA32(0);
        issueB(0, 0);
        asm volatile("cp.async.commit_group;" ::: "memory");
        cvtStoreA(0);
    } else {
        issueA(0, 0);
        issueB(0, 0);
        asm volatile("cp.async.commit_group;" ::: "memory");
    }

    for (int c = 0; c < nc; c++) {
        int cur = c & 1;
        if (c + 1 < nc) {
            if (AFP32) {
                ldgA32((c + 1) << 5);
                issueB((c + 1) << 5, cur ^ 1);
            } else {
                issueA((c + 1) << 5, cur ^ 1);
                issueB((c + 1) << 5, cur ^ 1);
            }
            asm volatile("cp.async.commit_group;" ::: "memory");
            asm volatile("cp.async.wait_group 1;" ::: "memory");
        } else {
            asm volatile("cp.async.wait_group 0;" ::: "memory");
        }
        __syncthreads();

        uint32_t base = sbase + cur * STAGE;
        uint32_t aAhi = base, aAlo = base + OFF_ALO;
        uint32_t aBhi = base + OFF_BHI, aBlo = base + OFF_BLO;

        #pragma unroll
        for (int kk = 0; kk < 2; kk++) {
            int kb = kk * 16;
            uint32_t ahi[4][4], alo[4][4];
            #pragma unroll
            for (int im = 0; im < 4; im++) {
                int row = wm + im * 16 + (lane & 15);
                uint32_t off = row * 80 + kb * 2 + ((lane >> 4) << 4);
                ldsm_x4(ahi[im], aAhi + off);
                ldsm_x4(alo[im], aAlo + off);
            }
            #pragma unroll
            for (int jn = 0; jn < 4; jn++) {
                int n = wn + jn * 8;
                uint32_t off = (kb + (lane & 15)) * 272 + n * 2;
                uint32_t bhi[2], blo[2];
                ldsm_x2t(bhi, aBhi + off);
                ldsm_x2t(blo, aBlo + off);
                #pragma unroll
                for (int im = 0; im < 4; im++) {
                    mma_bf16(acc[im][jn], ahi[im], bhi);
                    mma_bf16(acc[im][jn], alo[im], bhi);
                    mma_bf16(acc[im][jn], ahi[im], blo);
                }
            }
        }

        if (AFP32 && c + 1 < nc) cvtStoreA(cur ^ 1);
        if (!AFP32 || c + 1 >= nc) { if (c + 1 < nc) { } }
        __syncthreads();
    }

    int tr = lane >> 2, tc = (lane & 3) << 1;
    #pragma unroll
    for (int im = 0; im < 4; im++) {
        #pragma unroll
        for (int half = 0; half < 2; half++) {
            int grow = bm + wm + im * 16 + tr + half * 8;
            size_t ro;
            if (remap) {
                int t = grow >> 7, b = grow & 127;
                ro = ((size_t)b * TS + t) * (size_t)N;
            } else {
                ro = (size_t)grow * (size_t)N;
            }
            #pragma unroll
            for (int jn = 0; jn < 4; jn++) {
                int gc = bn + wn + jn * 8 + tc;
                if (gc < N) {
                    float v0 = acc[im][jn][half * 2 + 0] + bias[gc];
                    float v1 = acc[im][jn][half * 2 + 1] + bias[gc + 1];
                    if (relu) { v0 = fmaxf(v0, 0.f); v1 = fmaxf(v1, 0.f); }
                    if (C) *(float2*)(C + ro + gc) = make_float2(v0, v1);
                    if (Chi) {
                        __nv_bfloat16 h0 = __float2bfloat16(v0);
                        __nv_bfloat16 h1 = __float2bfloat16(v1);
                        *(uint32_t*)(Chi + ro + gc) = packbf(h0, h1);
                        __nv_bfloat16 l0 = __float2bfloat16(v0 - __bfloat162float(h0));
                        __nv_bfloat16 l1 = __float2bfloat16(v1 - __bfloat162float(h1));
                        *(uint32_t*)(Clo + ro + gc) = packbf(l0, l1);
                    }
                }
            }
        }
    }
}

// ---------------- token embedding gather -> bf16 pair ----------------
__global__ void gather_kernel(const int* __restrict__ target,
                              const float* __restrict__ emb)
{
    int row = blockIdx.x;
    int e = threadIdx.x;
    int t = row >> 7, b = row & 127;
    int tok = (t == 0) ? 1 : target[b * 48 + t];
    float v = emb[(size_t)tok * 256 + e];
    __nv_bfloat16 h = __float2bfloat16(v);
    g_etok_hi[(size_t)row * 256 + e] = h;
    g_etok_lo[(size_t)row * 256 + e] = __float2bfloat16(v - __bfloat162float(h));
}

// ---------------- persistent step loop ----------------
// dynamic smem (floats):
//   sFW1  [0..32767]       featw1[bid]   64x512
//   sFEAT [32768..49151]   features[bid] 64x256
//   sW    [49152..52271]   gru_k[:256] slice: [3 gates][4 u][260]  (persistent)
//   work  [52272..57391]   A: 2048; B: 1088; C: sC[2][128][20]=5120
__global__ __launch_bounds__(256) void step_loop_kernel(
    const float* __restrict__ W2, const float* __restrict__ V,
    const float* __restrict__ bV, const float* __restrict__ b2,
    const float* __restrict__ gru_k, const float* __restrict__ gru_b)
{
    extern __shared__ float dsm[];
    float* sFW1  = dsm;
    float* sFEAT = dsm + 32768;
    float* sW    = dsm + 49152;
    float* work  = dsm + 52272;

    const int bid = blockIdx.x;
    const int tid = threadIdx.x;
    unsigned bar = g_epoch;
    const unsigned bar0 = bar;

    // persistent caches
    for (int j = tid; j < 8192; j += 256)
        *(float4*)&sFW1[j * 4] = *(const float4*)(g_featw1 + (size_t)bid * 32768 + j * 4);
    for (int j = tid; j < 4096; j += 256)
        *(float4*)&sFEAT[j * 4] = *(const float4*)(g_features + (size_t)bid * 16384 + j * 4);
    for (int idx = tid; idx < 3072; idx += 256) {
        int g = idx >> 10, rem = idx & 1023;
        int j = rem >> 8, k = rem & 255;
        sW[g * 1040 + j * 260 + k] = gru_k[(size_t)k * 1536 + g * 512 + bid * 4 + j];
    }
    __syncthreads();

    for (int t = 0; t < TS; t++) {
        // ---- Phase A: hidw2 = states[t-1] @ W2 (K-split 2, 32x32 tiles) ----
        if (t > 0) {
            float* As = work;
            float* Bs = work + 1024;
            int z  = bid >> 6;
            int rr = bid & 63;
            int bm = (rr >> 4) * 32;
            int bn = (rr & 15) * 32;
            const float* A = g_states + (size_t)(t - 1) * 65536;
            float* C = g_hidw2 + z * 65536;
            int kbeg = z * 256;
            int arow = tid >> 3, akc = (tid & 7) * 2;
            int bkr = tid >> 4, bnc = (tid & 15) * 2;
            int tx = tid & 15, ty = tid >> 4;
            float a00 = 0.f, a01 = 0.f, a10 = 0.f, a11 = 0.f;

            float2 ra = *(const float2*)(A + (size_t)(bm + arow) * 512 + kbeg + akc);
            float2 rb = *(const float2*)(W2 + (size_t)(kbeg + bkr) * 512 + bn + bnc);
            As[akc * 32 + arow] = ra.x;
            As[(akc + 1) * 32 + arow] = ra.y;
            Bs[bkr * 32 + bnc] = rb.x;
            Bs[bkr * 32 + bnc + 1] = rb.y;
            __syncthreads();

            for (int c = 0; c < 16; c++) {
                int cur = c & 1;
                if (c + 1 < 16) {
                    int k0 = kbeg + (c + 1) * 16;
                    ra = *(const float2*)(A + (size_t)(bm + arow) * 512 + k0 + akc);
                    rb = *(const float2*)(W2 + (size_t)(k0 + bkr) * 512 + bn + bnc);
                }
                float* Ac = As + cur * 512;
                float* Bc = Bs + cur * 512;
                #pragma unroll
                for (int k = 0; k < 16; k++) {
                    float2 a = *(const float2*)&Ac[k * 32 + ty * 2];
                    float2 b = *(const float2*)&Bc[k * 32 + tx * 2];
                    a00 = fmaf(a.x, b.x, a00); a01 = fmaf(a.x, b.y, a01);
                    a10 = fmaf(a.y, b.x, a10); a11 = fmaf(a.y, b.y, a11);
                }
                if (c + 1 < 16) {
                    int nxt = cur ^ 1;
                    As[nxt * 512 + akc * 32 + arow] = ra.x;
                    As[nxt * 512 + (akc + 1) * 32 + arow] = ra.y;
                    Bs[nxt * 512 + bkr * 32 + bnc] = rb.x;
                    Bs[nxt * 512 + bkr * 32 + bnc + 1] = rb.y;
                    __syncthreads();
                }
            }
            int r0 = bm + ty * 2, c0 = bn + tx * 2;
            C[(size_t)(r0 + 0) * 512 + c0 + 0] = a00;
            C[(size_t)(r0 + 0) * 512 + c0 + 1] = a01;
            C[(size_t)(r0 + 1) * 512 + c0 + 0] = a10;
            C[(size_t)(r0 + 1) * 512 + c0 + 1] = a11;
            grid_bar2(bid, tid, ++bar);
        }

        // ---- Phase B: Bahdanau attention (smem-resident featw1/features) ----
        {
            float* hw2 = work;
            float* sV  = work + 512;
            float* sl  = work + 1024;
            int b = bid;
            if (t > 0) {
                hw2[tid]       = g_hidw2[b * 512 + tid]       + g_hidw2[65536 + b * 512 + tid]       + b2[tid];
                hw2[tid + 256] = g_hidw2[b * 512 + tid + 256] + g_hidw2[65536 + b * 512 + tid + 256] + b2[tid + 256];
            } else {
                hw2[tid]       = b2[tid];
                hw2[tid + 256] = b2[tid + 256];
            }
            sV[tid]       = V[tid];
            sV[tid + 256] = V[tid + 256];
            __syncthreads();

            int w = tid >> 5, lane = tid & 31;
            #pragma unroll
            for (int p = 0; p < 8; p++) {
                int l = w * 8 + p;
                const float* row = sFW1 + l * 512;
                float a = 0.f;
                #pragma unroll
                for (int j = 0; j < 16; j++) {
                    int u = lane + j * 32;
                    float s = tanh_apx(row[u] + hw2[u]);
                    a = fmaf(s, sV[u], a);
                }
                #pragma unroll
                for (int o = 16; o; o >>= 1) a += __shfl_xor_sync(0xffffffffu, a, o);
                if (lane == 0) sl[l] = a + bV[0];
            }
            __syncthreads();

            if (tid < 32) {
                float v0 = sl[tid], v1 = sl[tid + 32];
                float m = fmaxf(v0, v1);
                #pragma unroll
                for (int o = 16; o; o >>= 1) m = fmaxf(m, __shfl_xor_sync(0xffffffffu, m, o));
                float e0 = __expf(v0 - m), e1 = __expf(v1 - m);
                float s = e0 + e1;
                #pragma unroll
                for (int o = 16; o; o >>= 1) s += __shfl_xor_sync(0xffffffffu, s, o);
                float inv = 1.0f / s;
                sl[tid] = e0 * inv;
                sl[tid + 32] = e1 * inv;
            }
            __syncthreads();

            float c = 0.f;
            #pragma unroll 8
            for (int l = 0; l < 64; l++)
                c = fmaf(sl[l], sFEAT[l * 256 + tid], c);
            g_context[b * 256 + tid] = c;
        }
        grid_bar2(bid, tid, ++bar);

        // ---- Phase C+D: block = (all 128 batches) x (4 units), persistent weights ----
        {
            float* sC = work;                 // [2][128][20]
            const int j = tid & 3;
            const int brow = tid >> 2;        // 0..63 (handles brow, brow+64)
            const int u = bid * 4 + j;

            float az0 = 0.f, ar0 = 0.f, ah0 = 0.f;
            float az1 = 0.f, ar1 = 0.f, ah1 = 0.f;

            float4 pf[2];
            #pragma unroll
            for (int i = 0; i < 2; i++) {
                int fidx = tid + (i << 8);
                int row = fidx >> 2, q = fidx & 3;
                pf[i] = *(const float4*)(g_context + row * 256 + q * 4);
            }

            for (int c = 0; c < 16; c++) {
                float* sCc = sC + (c & 1) * 2560;
                #pragma unroll
                for (int i = 0; i < 2; i++) {
                    int fidx = tid + (i << 8);
                    int row = fidx >> 2, q = fidx & 3;
                    *(float4*)&sCc[row * 20 + q * 4] = pf[i];
                }
                __syncthreads();
                if (c + 1 < 16) {
                    int k0n = (c + 1) * 16;
                    #pragma unroll
                    for (int i = 0; i < 2; i++) {
                        int fidx = tid + (i << 8);
                        int row = fidx >> 2, q = fidx & 3;
                        pf[i] = *(const float4*)(g_context + row * 256 + k0n + q * 4);
                    }
                }
                int k0 = c * 16;
                #pragma unroll
                for (int q = 0; q < 4; q++) {
                    float4 a0 = *(const float4*)&sCc[brow * 20 + q * 4];
                    float4 a1 = *(const float4*)&sCc[(brow + 64) * 20 + q * 4];
                    float4 wz = *(const float4*)&sW[j * 260 + k0 + q * 4];
                    float4 wr = *(const float4*)&sW[1040 + j * 260 + k0 + q * 4];
                    float4 wh = *(const float4*)&sW[2080 + j * 260 + k0 + q * 4];
                    az0 = fmaf(a0.x, wz.x, az0); az0 = fmaf(a0.y, wz.y, az0);
                    az0 = fmaf(a0.z, wz.z, az0); az0 = fmaf(a0.w, wz.w, az0);
                    ar0 = fmaf(a0.x, wr.x, ar0); ar0 = fmaf(a0.y, wr.y, ar0);
                    ar0 = fmaf(a0.z, wr.z, ar0); ar0 = fmaf(a0.w, wr.w, ar0);
                    ah0 = fmaf(a0.x, wh.x, ah0); ah0 = fmaf(a0.y, wh.y, ah0);
                    ah0 = fmaf(a0.z, wh.z, ah0); ah0 = fmaf(a0.w, wh.w, ah0);
                    az1 = fmaf(a1.x, wz.x, az1); az1 = fmaf(a1.y, wz.y, az1);
                    az1 = fmaf(a1.z, wz.z, az1); az1 = fmaf(a1.w, wz.w, az1);
                    ar1 = fmaf(a1.x, wr.x, ar1); ar1 = fmaf(a1.y, wr.y, ar1);
                    ar1 = fmaf(a1.z, wr.z, ar1); ar1 = fmaf(a1.w, wr.w, ar1);
                    ah1 = fmaf(a1.x, wh.x, ah1); ah1 = fmaf(a1.y, wh.y, ah1);
                    ah1 = fmaf(a1.z, wh.z, ah1); ah1 = fmaf(a1.w, wh.w, ah1);
                }
            }

            float rz = gru_b[1536 + u];
            float rr = gru_b[2048 + u];
            float rh = gru_b[2560 + u];
            #pragma unroll
            for (int i = 0; i < 2; i++) {
                int b = brow + i * 64;
                size_t r = (size_t)t * 128 + b;
                float xz = (i ? az1 : az0) + g_embmx[r * 1536 + u];
                float xr = (i ? ar1 : ar0) + g_embmx[r * 1536 + 512 + u];
                float xh = (i ? ah1 : ah0) + g_embmx[r * 1536 + 1024 + u];
                float z  = 1.f / (1.f + __expf(-(xz + rz)));
                float rg = 1.f / (1.f + __expf(-(xr + rr)));
                float hh = tanh_apx(xh + rg * rh);
                float st = (1.f - z) * hh;
                g_states[r * 512 + u] = st;
                __nv_bfloat16 h = __float2bfloat16(st);
                g_st_hi[r * 512 + u] = h;
                g_st_lo[r * 512 + u] = __float2bfloat16(st - __bfloat162float(h));
            }
        }
        grid_bar2(bid, tid, ++bar);
    }

    if (bid == 0 && tid == 0) g_epoch = bar0 + (unsigned)(3 * TS - 1);
}

// ---------------- launch ----------------
extern "C" void kernel_launch(void* const* d_in, const int* in_sizes, int n_in,
                              void* d_out, int out_size)
{
    const float* img    = (const float*)d_in[0];
    const int*   target = (const int*)  d_in[1];
    const float* W_fc   = (const float*)d_in[2];
    const float* b_fc   = (const float*)d_in[3];
    const float* W1     = (const float*)d_in[4];
    const float* b1     = (const float*)d_in[5];
    const float* W2     = (const float*)d_in[6];
    const float* b2     = (const float*)d_in[7];
    const float* V      = (const float*)d_in[8];
    const float* bV     = (const float*)d_in[9];
    const float* emb    = (const float*)d_in[10];
    const float* gru_k  = (const float*)d_in[11];
    /* d_in[12] = gru_rk : dead (zero GRU state) */
    const float* gru_b  = (const float*)d_in[13];
    const float* fc1_w  = (const float*)d_in[14];
    const float* fc1_b  = (const float*)d_in[15];
    const float* fc2_w  = (const float*)d_in[16];
    const float* fc2_b  = (const float*)d_in[17];
    float* out = (float*)d_out;

    float *features, *featw1, *embmx;
    __nv_bfloat16 *wfcH, *wfcL, *featH, *featL, *w1H, *w1L;
    __nv_bfloat16 *gk2H, *gk2L, *stH, *stL, *f1wH, *f1wL, *f1oH, *f1oL, *f2wH, *f2wL;
    __nv_bfloat16 *etH, *etL;
    cudaGetSymbolAddress((void**)&features, g_features);
    cudaGetSymbolAddress((void**)&featw1,  g_featw1);
    cudaGetSymbolAddress((void**)&embmx,   g_embmx);
    cudaGetSymbolAddress((void**)&wfcH, g_wfc_hi);  cudaGetSymbolAddress((void**)&wfcL, g_wfc_lo);
    cudaGetSymbolAddress((void**)&featH, g_feat_hi);cudaGetSymbolAddress((void**)&featL, g_feat_lo);
    cudaGetSymbolAddress((void**)&w1H, g_w1_hi);    cudaGetSymbolAddress((void**)&w1L, g_w1_lo);
    cudaGetSymbolAddress((void**)&etH, g_etok_hi);  cudaGetSymbolAddress((void**)&etL, g_etok_lo);
    cudaGetSymbolAddress((void**)&gk2H, g_gk2_hi);  cudaGetSymbolAddress((void**)&gk2L, g_gk2_lo);
    cudaGetSymbolAddress((void**)&stH, g_st_hi);    cudaGetSymbolAddress((void**)&stL, g_st_lo);
    cudaGetSymbolAddress((void**)&f1wH, g_f1w_hi);  cudaGetSymbolAddress((void**)&f1wL, g_f1w_lo);
    cudaGetSymbolAddress((void**)&f1oH, g_f1o_hi);  cudaGetSymbolAddress((void**)&f1oL, g_f1o_lo);
    cudaGetSymbolAddress((void**)&f2wH, g_f2w_hi);  cudaGetSymbolAddress((void**)&f2wL, g_f2w_lo);

    const int SMEM_SZ = 2 * STAGE;
    cudaFuncSetAttribute(mma_gemm_bf<false>, cudaFuncAttributeMaxDynamicSharedMemorySize, SMEM_SZ);
    cudaFuncSetAttribute(mma_gemm_bf<true>,  cudaFuncAttributeMaxDynamicSharedMemorySize, SMEM_SZ);
    const int STEP_SMEM = 57392 * 4;   // 229568 B
    cudaFuncSetAttribute(step_loop_kernel, cudaFuncAttributeMaxDynamicSharedMemorySize, STEP_SMEM);

    // weight converts (small) + gather
    cvt_pair<<<(2048 * 256 / 4 + 255) / 256, 256>>>(W_fc, wfcH, wfcL, 2048 * 256);
    cvt_pair<<<(256 * 512 / 4 + 255) / 256, 256>>>(W1, w1H, w1L, 256 * 512);
    cvt_pair<<<(256 * 1536 / 4 + 255) / 256, 256>>>(gru_k + 256 * 1536, gk2H, gk2L, 256 * 1536);
    cvt_pair<<<(512 * 512 / 4 + 255) / 256, 256>>>(fc1_w, f1wH, f1wL, 512 * 512);
    cvt_pair<<<(512 * 5000 / 4 + 255) / 256, 256>>>(fc2_w, f2wH, f2wL, 512 * 5000);
    gather_kernel<<<6016, 256>>>(target, emb);

    // encoder: fp32 img split in-kernel
    mma_gemm_bf<true><<<dim3(2, 64), 256, SMEM_SZ>>>(img, nullptr, nullptr, wfcH, wfcL, b_fc,
                                                     features, featH, featL, 8192, 256, 2048, 1, 0);
    mma_gemm_bf<false><<<dim3(4, 64), 256, SMEM_SZ>>>(nullptr, featH, featL, w1H, w1L, b1,
                                                      featw1, nullptr, nullptr, 8192, 512, 256, 0, 0);
    mma_gemm_bf<false><<<dim3(12, 47), 256, SMEM_SZ>>>(nullptr, etH, etL, gk2H, gk2L, gru_b,
                                                       embmx, nullptr, nullptr, 6016, 1536, 256, 0, 0);

    step_loop_kernel<<<128, 256, STEP_SMEM>>>(W2, V, bV, b2, gru_k, gru_b);

    mma_gemm_bf<false><<<dim3(4, 47), 256, SMEM_SZ>>>(nullptr, stH, stL, f1wH, f1wL, fc1_b,
                                                      nullptr, f1oH, f1oL, 6016, 512, 512, 0, 0);
    mma_gemm_bf<false><<<dim3(40, 47), 256, SMEM_SZ>>>(nullptr, f1oH, f1oL, f2wH, f2wL, fc2_b,
                                                       out, nullptr, nullptr, 6016, 5000, 512, 0, 1);
}

// round 10
// speedup vs baseline: 1.0654x; 1.0654x over previous
#include <cuda_runtime.h>
#include <cuda_bf16.h>
#include <cstdint>

#define TS 47

// ---------------- fp32 scratch ----------------
__device__ __align__(128) float g_features[8192 * 256];
__device__ __align__(128) float g_featw1 [8192 * 512];
__device__ __align__(128) float g_embmx  [6016 * 1536];
__device__ __align__(128) float g_hidw2  [2 * 128 * 512];
__device__ __align__(128) float g_context[128 * 256];
__device__ __align__(128) float g_states [6016 * 512];

// ---------------- bf16 hi/lo pairs ----------------
__device__ __align__(128) __nv_bfloat16 g_img_hi [8192 * 2048], g_img_lo [8192 * 2048];
__device__ __align__(128) __nv_bfloat16 g_wfc_hi [2048 * 256],  g_wfc_lo [2048 * 256];
__device__ __align__(128) __nv_bfloat16 g_feat_hi[8192 * 256],  g_feat_lo[8192 * 256];
__device__ __align__(128) __nv_bfloat16 g_w1_hi  [256 * 512],   g_w1_lo  [256 * 512];
__device__ __align__(128) __nv_bfloat16 g_etok_hi[6016 * 256],  g_etok_lo[6016 * 256];
__device__ __align__(128) __nv_bfloat16 g_gk2_hi [256 * 1536],  g_gk2_lo [256 * 1536];
__device__ __align__(128) __nv_bfloat16 g_st_hi  [6016 * 512],  g_st_lo  [6016 * 512];
__device__ __align__(128) __nv_bfloat16 g_f1w_hi [512 * 512],   g_f1w_lo [512 * 512];
__device__ __align__(128) __nv_bfloat16 g_f1o_hi [6016 * 512],  g_f1o_lo [6016 * 512];
__device__ __align__(128) __nv_bfloat16 g_f2w_hi [512 * 5000],  g_f2w_lo [512 * 5000];

// ---------------- barrier state (monotonic, replay-safe) ----------------
__device__ unsigned g_flags[128];
__device__ unsigned g_release;
__device__ unsigned g_epoch;

// ---------------- helpers ----------------
__device__ __forceinline__ float tanh_apx(float x) {
    float y;
    asm("tanh.approx.f32 %0, %1;" : "=f"(y) : "f"(x));
    return y;
}
__device__ __forceinline__ unsigned ld_acq(const unsigned* p) {
    unsigned v;
    asm volatile("ld.acquire.gpu.global.u32 %0, [%1];" : "=r"(v) : "l"(p));
    return v;
}
__device__ __forceinline__ void st_rel(unsigned* p, unsigned v) {
    asm volatile("st.release.gpu.global.u32 [%0], %1;" :: "l"(p), "r"(v) : "memory");
}
__device__ __forceinline__ void grid_bar2(int bid, int tid, unsigned tgt) {
    __syncthreads();
    if (bid == 0) {
        if (tid > 0 && tid < 128) {
            while ((int)(ld_acq(&g_flags[tid]) - tgt) < 0) { }
        }
        __syncthreads();
        if (tid == 0) st_rel(&g_release, tgt);
    } else {
        if (tid == 0) {
            st_rel(&g_flags[bid], tgt);
            while ((int)(ld_acq(&g_release) - tgt) < 0) { }
        }
        __syncthreads();
    }
}

__device__ __forceinline__ uint32_t smem_u32(const void* p) {
    uint32_t a;
    asm("{ .reg .u64 t; cvta.to.shared.u64 t, %1; cvt.u32.u64 %0, t; }"
        : "=r"(a) : "l"(p));
    return a;
}
__device__ __forceinline__ void ldsm_x4(uint32_t* r, uint32_t addr) {
    asm volatile("ldmatrix.sync.aligned.m8n8.x4.shared.b16 {%0,%1,%2,%3}, [%4];"
        : "=r"(r[0]), "=r"(r[1]), "=r"(r[2]), "=r"(r[3]) : "r"(addr));
}
__device__ __forceinline__ void ldsm_x2t(uint32_t* r, uint32_t addr) {
    asm volatile("ldmatrix.sync.aligned.m8n8.x2.trans.shared.b16 {%0,%1}, [%2];"
        : "=r"(r[0]), "=r"(r[1]) : "r"(addr));
}
__device__ __forceinline__ void mma_bf16(float* c, const uint32_t* a, const uint32_t* b) {
    asm volatile("mma.sync.aligned.m16n8k16.row.col.f32.bf16.bf16.f32 "
        "{%0,%1,%2,%3},{%4,%5,%6,%7},{%8,%9},{%0,%1,%2,%3};"
        : "+f"(c[0]), "+f"(c[1]), "+f"(c[2]), "+f"(c[3])
        : "r"(a[0]), "r"(a[1]), "r"(a[2]), "r"(a[3]), "r"(b[0]), "r"(b[1]));
}
__device__ __forceinline__ uint32_t packbf(__nv_bfloat16 a, __nv_bfloat16 b) {
    __nv_bfloat162 t = __halves2bfloat162(a, b);
    return *(uint32_t*)&t;
}
__device__ __forceinline__ void cpasync16(uint32_t sa, const void* ga, int sz) {
    asm volatile("cp.async.cg.shared.global [%0], [%1], 16, %2;"
                 :: "r"(sa), "l"(ga), "r"(sz) : "memory");
}
#define CP_COMMIT() asm volatile("cp.async.commit_group;" ::: "memory")

// ---------------- fp32 -> bf16 hi/lo convert ----------------
__global__ void cvt_pair(const float* __restrict__ s,
                         __nv_bfloat16* __restrict__ hi,
                         __nv_bfloat16* __restrict__ lo, int n)
{
    int i = (blockIdx.x * 256 + threadIdx.x) * 4;
    if (i >= n) return;
    float4 v = *(const float4*)(s + i);
    __nv_bfloat16 hx = __float2bfloat16(v.x), hy = __float2bfloat16(v.y);
    __nv_bfloat16 hz = __float2bfloat16(v.z), hw = __float2bfloat16(v.w);
    *(uint2*)(hi + i) = make_uint2(packbf(hx, hy), packbf(hz, hw));
    __nv_bfloat16 lx = __float2bfloat16(v.x - __bfloat162float(hx));
    __nv_bfloat16 ly = __float2bfloat16(v.y - __bfloat162float(hy));
    __nv_bfloat16 lz = __float2bfloat16(v.z - __bfloat162float(hz));
    __nv_bfloat16 lw = __float2bfloat16(v.w - __bfloat162float(hw));
    *(uint2*)(lo + i) = make_uint2(packbf(lx, ly), packbf(lz, lw));
}

// ---------------- bf16-pair tensor-core GEMM, cp.async double buffer (R8) ----------------
#define OFF_ALO 10240
#define OFF_BHI 20480
#define OFF_BLO 29184
#define STAGE   37888

__global__ void __launch_bounds__(256, 2) mma_gemm_bf(
    const __nv_bfloat16* __restrict__ Ahi, const __nv_bfloat16* __restrict__ Alo,
    const __nv_bfloat16* __restrict__ Bhi, const __nv_bfloat16* __restrict__ Blo,
    const float* __restrict__ bias, float* __restrict__ C,
    __nv_bfloat16* __restrict__ Chi, __nv_bfloat16* __restrict__ Clo,
    int M, int N, int K, int relu, int remap)
{
    extern __shared__ char smem[];
    const int tid = threadIdx.x;
    const int wid = tid >> 5, lane = tid & 31;
    const int bm = blockIdx.y * 128, bn = blockIdx.x * 128;
    const int wm = (wid >> 2) * 64;
    const int wn = (wid & 3) * 32;
    const uint32_t sbase = smem_u32(smem);

    float acc[4][4][4] = {};
    const int nc = K >> 5;

    auto issue = [&](int k0, int s) {
        uint32_t sb = sbase + s * STAGE;
        #pragma unroll
        for (int i = 0; i < 2; i++) {
            int task = tid + (i << 8);
            int m = task >> 2, k8 = (task & 3) << 3;
            uint32_t sa = sb + m * 80 + (k8 << 1);
            size_t go = (size_t)(bm + m) * K + k0 + k8;
            cpasync16(sa, Ahi + go, 16);
            cpasync16(sa + OFF_ALO, Alo + go, 16);
        }
        #pragma unroll
        for (int i = 0; i < 2; i++) {
            int task = tid + (i << 8);
            int kk = task >> 4, n8 = (task & 15) << 3;
            int gc = bn + n8;
            uint32_t sa = sb + OFF_BHI + kk * 272 + (n8 << 1);
            size_t go = (size_t)(k0 + kk) * N + gc;
            int sz = (gc + 8 <= N) ? 16 : 0;
            cpasync16(sa, Bhi + go, sz);
            cpasync16(sa + (OFF_BLO - OFF_BHI), Blo + go, sz);
        }
        CP_COMMIT();
    };

    issue(0, 0);

    for (int c = 0; c < nc; c++) {
        int cur = c & 1;
        if (c + 1 < nc) {
            issue((c + 1) << 5, cur ^ 1);
            asm volatile("cp.async.wait_group 1;" ::: "memory");
        } else {
            asm volatile("cp.async.wait_group 0;" ::: "memory");
        }
        __syncthreads();

        uint32_t base = sbase + cur * STAGE;
        uint32_t aAhi = base, aAlo = base + OFF_ALO;
        uint32_t aBhi = base + OFF_BHI, aBlo = base + OFF_BLO;

        #pragma unroll
        for (int kk = 0; kk < 2; kk++) {
            int kb = kk * 16;
            uint32_t ahi[4][4], alo[4][4];
            #pragma unroll
            for (int im = 0; im < 4; im++) {
                int row = wm + im * 16 + (lane & 15);
                uint32_t off = row * 80 + kb * 2 + ((lane >> 4) << 4);
                ldsm_x4(ahi[im], aAhi + off);
                ldsm_x4(alo[im], aAlo + off);
            }
            #pragma unroll
            for (int jn = 0; jn < 4; jn++) {
                int n = wn + jn * 8;
                uint32_t off = (kb + (lane & 15)) * 272 + n * 2;
                uint32_t bhi[2], blo[2];
                ldsm_x2t(bhi, aBhi + off);
                ldsm_x2t(blo, aBlo + off);
                #pragma unroll
                for (int im = 0; im < 4; im++) {
                    mma_bf16(acc[im][jn], ahi[im], bhi);
                    mma_bf16(acc[im][jn], alo[im], bhi);
                    mma_bf16(acc[im][jn], ahi[im], blo);
                }
            }
        }
        __syncthreads();
    }

    int tr = lane >> 2, tc = (lane & 3) << 1;
    #pragma unroll
    for (int im = 0; im < 4; im++) {
        #pragma unroll
        for (int half = 0; half < 2; half++) {
            int grow = bm + wm + im * 16 + tr + half * 8;
            size_t ro;
            if (remap) {
                int t = grow >> 7, b = grow & 127;
                ro = ((size_t)b * TS + t) * (size_t)N;
            } else {
                ro = (size_t)grow * (size_t)N;
            }
            #pragma unroll
            for (int jn = 0; jn < 4; jn++) {
                int gc = bn + wn + jn * 8 + tc;
                if (gc < N) {
                    float v0 = acc[im][jn][half * 2 + 0] + bias[gc];
                    float v1 = acc[im][jn][half * 2 + 1] + bias[gc + 1];
                    if (relu) { v0 = fmaxf(v0, 0.f); v1 = fmaxf(v1, 0.f); }
                    if (C) *(float2*)(C + ro + gc) = make_float2(v0, v1);
                    if (Chi) {
                        __nv_bfloat16 h0 = __float2bfloat16(v0);
                        __nv_bfloat16 h1 = __float2bfloat16(v1);
                        *(uint32_t*)(Chi + ro + gc) = packbf(h0, h1);
                        __nv_bfloat16 l0 = __float2bfloat16(v0 - __bfloat162float(h0));
                        __nv_bfloat16 l1 = __float2bfloat16(v1 - __bfloat162float(h1));
                        *(uint32_t*)(Clo + ro + gc) = packbf(l0, l1);
                    }
                }
            }
        }
    }
}

// ---------------- token embedding gather -> bf16 pair ----------------
__global__ void gather_kernel(const int* __restrict__ target,
                              const float* __restrict__ emb)
{
    int row = blockIdx.x;
    int e = threadIdx.x;
    int t = row >> 7, b = row & 127;
    int tok = (t == 0) ? 1 : target[b * 48 + t];
    float v = emb[(size_t)tok * 256 + e];
    __nv_bfloat16 h = __float2bfloat16(v);
    g_etok_hi[(size_t)row * 256 + e] = h;
    g_etok_lo[(size_t)row * 256 + e] = __float2bfloat16(v - __bfloat162float(h));
}

// ---------------- persistent step loop (cp.async deep pipelines) ----------------
// dynamic smem (floats):
//   sFW1  [0..32767]       featw1[bid]   64x512
//   sFEAT [32768..49151]   features[bid] 64x256
//   work  [49152..57855]   A: 4 stages x 2048 (As 32x32 + Bs 32x32)
//                          B: 1088
//                          C: sA 4096 + 3 stages x 1536
__global__ __launch_bounds__(256) void step_loop_kernel(
    const float* __restrict__ W2, const float* __restrict__ V,
    const float* __restrict__ bV, const float* __restrict__ b2,
    const float* __restrict__ gru_k, const float* __restrict__ gru_b)
{
    extern __shared__ float dsm[];
    float* sFW1  = dsm;
    float* sFEAT = dsm + 32768;
    float* work  = dsm + 49152;

    const int bid = blockIdx.x;
    const int tid = threadIdx.x;
    unsigned bar = g_epoch;
    const unsigned bar0 = bar;

    // persistent caches (featw1/features for this batch element)
    for (int j = tid; j < 8192; j += 256)
        *(float4*)&sFW1[j * 4] = *(const float4*)(g_featw1 + (size_t)bid * 32768 + j * 4);
    for (int j = tid; j < 4096; j += 256)
        *(float4*)&sFEAT[j * 4] = *(const float4*)(g_features + (size_t)bid * 16384 + j * 4);
    __syncthreads();

    for (int t = 0; t < TS; t++) {
        // ---- Phase A: hidw2 = states[t-1] @ W2 (K-split 2, 32x32 tiles, 4-stage cp.async) ----
        if (t > 0) {
            int z  = bid >> 6;
            int rr = bid & 63;
            int bm = (rr >> 4) * 32;
            int bn = (rr & 15) * 32;
            const float* A = g_states + (size_t)(t - 1) * 65536;
            float* C = g_hidw2 + z * 65536;
            int kbeg = z * 256;
            int ty = tid >> 4, tx = tid & 15;
            int lrow = tid >> 3, lk4 = (tid & 7) << 2;

            auto issueA = [&](int c) {
                int k0 = kbeg + c * 32;
                uint32_t st = smem_u32(work + (c & 3) * 2048);
                cpasync16(st + (lrow * 32 + lk4) * 4,
                          A + (size_t)(bm + lrow) * 512 + k0 + lk4, 16);
                cpasync16(st + (1024 + lrow * 32 + lk4) * 4,
                          W2 + (size_t)(k0 + lrow) * 512 + bn + lk4, 16);
                CP_COMMIT();
            };
            issueA(0); issueA(1); issueA(2);

            float a00 = 0.f, a01 = 0.f, a10 = 0.f, a11 = 0.f;
            for (int c = 0; c < 8; c++) {
                if (c <= 5)      asm volatile("cp.async.wait_group 2;" ::: "memory");
                else if (c == 6) asm volatile("cp.async.wait_group 1;" ::: "memory");
                else             asm volatile("cp.async.wait_group 0;" ::: "memory");
                __syncthreads();
                const float* As = work + (c & 3) * 2048;
                const float* Bs = As + 1024;
                #pragma unroll
                for (int k = 0; k < 32; k++) {
                    float a0 = As[(ty * 2 + 0) * 32 + k];
                    float a1 = As[(ty * 2 + 1) * 32 + k];
                    float2 b = *(const float2*)&Bs[k * 32 + tx * 2];
                    a00 = fmaf(a0, b.x, a00); a01 = fmaf(a0, b.y, a01);
                    a10 = fmaf(a1, b.x, a10); a11 = fmaf(a1, b.y, a11);
                }
                __syncthreads();
                if (c + 3 < 8) issueA(c + 3);
            }
            int r0 = bm + ty * 2, c0 = bn + tx * 2;
            C[(size_t)(r0 + 0) * 512 + c0 + 0] = a00;
            C[(size_t)(r0 + 0) * 512 + c0 + 1] = a01;
            C[(size_t)(r0 + 1) * 512 + c0 + 0] = a10;
            C[(size_t)(r0 + 1) * 512 + c0 + 1] = a11;
            grid_bar2(bid, tid, ++bar);
        }

        // ---- Phase B: Bahdanau attention (smem-resident featw1/features) ----
        {
            float* hw2 = work;
            float* sV  = work + 512;
            float* sl  = work + 1024;
            int b = bid;
            if (t > 0) {
                hw2[tid]       = g_hidw2[b * 512 + tid]       + g_hidw2[65536 + b * 512 + tid]       + b2[tid];
                hw2[tid + 256] = g_hidw2[b * 512 + tid + 256] + g_hidw2[65536 + b * 512 + tid + 256] + b2[tid + 256];
            } else {
                hw2[tid]       = b2[tid];
                hw2[tid + 256] = b2[tid + 256];
            }
            sV[tid]       = V[tid];
            sV[tid + 256] = V[tid + 256];
            __syncthreads();

            int w = tid >> 5, lane = tid & 31;
            #pragma unroll
            for (int p = 0; p < 8; p++) {
                int l = w * 8 + p;
                const float* row = sFW1 + l * 512;
                float a = 0.f;
                #pragma unroll
                for (int j = 0; j < 16; j++) {
                    int u = lane + j * 32;
                    float s = tanh_apx(row[u] + hw2[u]);
                    a = fmaf(s, sV[u], a);
                }
                #pragma unroll
                for (int o = 16; o; o >>= 1) a += __shfl_xor_sync(0xffffffffu, a, o);
                if (lane == 0) sl[l] = a + bV[0];
            }
            __syncthreads();

            if (tid < 32) {
                float v0 = sl[tid], v1 = sl[tid + 32];
                float m = fmaxf(v0, v1);
                #pragma unroll
                for (int o = 16; o; o >>= 1) m = fmaxf(m, __shfl_xor_sync(0xffffffffu, m, o));
                float e0 = __expf(v0 - m), e1 = __expf(v1 - m);
                float s = e0 + e1;
                #pragma unroll
                for (int o = 16; o; o >>= 1) s += __shfl_xor_sync(0xffffffffu, s, o);
                float inv = 1.0f / s;
                sl[tid] = e0 * inv;
                sl[tid + 32] = e1 * inv;
            }
            __syncthreads();

            float c = 0.f;
            #pragma unroll 8
            for (int l = 0; l < 64; l++)
                c = fmaf(sl[l], sFEAT[l * 256 + tid], c);
            g_context[b * 256 + tid] = c;
        }
        grid_bar2(bid, tid, ++bar);

        // ---- Phase C+D: mx = context @ gru_k[:256] + GRU pointwise (3-stage cp.async) ----
        {
            float* sA = work;            // 16 x 256 context tile
            float* sB = work + 4096;     // 3 stages x [3 gates][16 k][32 u]
            int u0 = (bid & 15) * 32;
            int b0 = (bid >> 4) * 16;
            int w = tid >> 5;
            int lane = tid & 31;
            int row0 = 2 * w, row1 = row0 + 1;

            auto issueC = [&](int c) {
                int k0 = c * 16;
                uint32_t st = smem_u32(sB + (c % 3) * 1536);
                #pragma unroll
                for (int i = 0; i < 2; i++) {
                    int idx = tid + (i << 8);
                    if (idx < 384) {
                        int g = idx >> 7, rem = idx & 127;
                        int k = rem >> 3, u4 = (rem & 7) << 2;
                        cpasync16(st + (g * 512 + k * 32 + u4) * 4,
                                  gru_k + (size_t)(k0 + k) * 1536 + g * 512 + u0 + u4, 16);
                    }
                }
            };
            // group 0: context tile + chunk 0
            {
                uint32_t stA = smem_u32(sA);
                #pragma unroll
                for (int i = 0; i < 4; i++) {
                    int f = tid + (i << 8);
                    int row = f >> 6, q = f & 63;
                    cpasync16(stA + (row * 256 + q * 4) * 4,
                              g_context + (size_t)(b0 + row) * 256 + q * 4, 16);
                }
                issueC(0);
                CP_COMMIT();
            }
            issueC(1); CP_COMMIT();

            float az0 = 0.f, ar0 = 0.f, ah0 = 0.f;
            float az1 = 0.f, ar1 = 0.f, ah1 = 0.f;

            for (int c = 0; c < 16; c++) {
                if (c < 15) asm volatile("cp.async.wait_group 1;" ::: "memory");
                else        asm volatile("cp.async.wait_group 0;" ::: "memory");
                __syncthreads();
                const float* Bs = sB + (c % 3) * 1536;
                int kb = c * 16;
                #pragma unroll
                for (int k = 0; k < 16; k++) {
                    float bz = Bs[k * 32 + lane];
                    float br = Bs[512 + k * 32 + lane];
                    float bh = Bs[1024 + k * 32 + lane];
                    float a0 = sA[row0 * 256 + kb + k];
                    float a1 = sA[row1 * 256 + kb + k];
                    az0 = fmaf(a0, bz, az0); ar0 = fmaf(a0, br, ar0); ah0 = fmaf(a0, bh, ah0);
                    az1 = fmaf(a1, bz, az1); ar1 = fmaf(a1, br, ar1); ah1 = fmaf(a1, bh, ah1);
                }
                __syncthreads();
                if (c + 2 < 16) { issueC(c + 2); CP_COMMIT(); }
            }

            int u = u0 + lane;
            float rz = gru_b[1536 + u];
            float rr = gru_b[2048 + u];
            float rh = gru_b[2560 + u];
            #pragma unroll
            for (int i = 0; i < 2; i++) {
                int b = b0 + row0 + i;
                size_t r = (size_t)t * 128 + b;
                float xz = (i ? az1 : az0) + g_embmx[r * 1536 + u];
                float xr = (i ? ar1 : ar0) + g_embmx[r * 1536 + 512 + u];
                float xh = (i ? ah1 : ah0) + g_embmx[r * 1536 + 1024 + u];
                float z  = 1.f / (1.f + __expf(-(xz + rz)));
                float rg = 1.f / (1.f + __expf(-(xr + rr)));
                float hh = tanh_apx(xh + rg * rh);
                float st = (1.f - z) * hh;
                g_states[r * 512 + u] = st;
                __nv_bfloat16 h = __float2bfloat16(st);
                g_st_hi[r * 512 + u] = h;
                g_st_lo[r * 512 + u] = __float2bfloat16(st - __bfloat162float(h));
            }
        }
        grid_bar2(bid, tid, ++bar);
    }

    if (bid == 0 && tid == 0) g_epoch = bar0 + (unsigned)(3 * TS - 1);
}

// ---------------- launch ----------------
extern "C" void kernel_launch(void* const* d_in, const int* in_sizes, int n_in,
                              void* d_out, int out_size)
{
    const float* img    = (const float*)d_in[0];
    const int*   target = (const int*)  d_in[1];
    const float* W_fc   = (const float*)d_in[2];
    const float* b_fc   = (const float*)d_in[3];
    const float* W1     = (const float*)d_in[4];
    const float* b1     = (const float*)d_in[5];
    const float* W2     = (const float*)d_in[6];
    const float* b2     = (const float*)d_in[7];
    const float* V      = (const float*)d_in[8];
    const float* bV     = (const float*)d_in[9];
    const float* emb    = (const float*)d_in[10];
    const float* gru_k  = (const float*)d_in[11];
    /* d_in[12] = gru_rk : dead (zero GRU state) */
    const float* gru_b  = (const float*)d_in[13];
    const float* fc1_w  = (const float*)d_in[14];
    const float* fc1_b  = (const float*)d_in[15];
    const float* fc2_w  = (const float*)d_in[16];
    const float* fc2_b  = (const float*)d_in[17];
    float* out = (float*)d_out;

    float *features, *featw1, *embmx;
    __nv_bfloat16 *imgH, *imgL, *wfcH, *wfcL, *featH, *featL, *w1H, *w1L;
    __nv_bfloat16 *gk2H, *gk2L, *stH, *stL, *f1wH, *f1wL, *f1oH, *f1oL, *f2wH, *f2wL;
    __nv_bfloat16 *etH, *etL;
    cudaGetSymbolAddress((void**)&features, g_features);
    cudaGetSymbolAddress((void**)&featw1,  g_featw1);
    cudaGetSymbolAddress((void**)&embmx,   g_embmx);
    cudaGetSymbolAddress((void**)&imgH, g_img_hi);  cudaGetSymbolAddress((void**)&imgL, g_img_lo);
    cudaGetSymbolAddress((void**)&wfcH, g_wfc_hi);  cudaGetSymbolAddress((void**)&wfcL, g_wfc_lo);
    cudaGetSymbolAddress((void**)&featH, g_feat_hi);cudaGetSymbolAddress((void**)&featL, g_feat_lo);
    cudaGetSymbolAddress((void**)&w1H, g_w1_hi);    cudaGetSymbolAddress((void**)&w1L, g_w1_lo);
    cudaGetSymbolAddress((void**)&etH, g_etok_hi);  cudaGetSymbolAddress((void**)&etL, g_etok_lo);
    cudaGetSymbolAddress((void**)&gk2H, g_gk2_hi);  cudaGetSymbolAddress((void**)&gk2L, g_gk2_lo);
    cudaGetSymbolAddress((void**)&stH, g_st_hi);    cudaGetSymbolAddress((void**)&stL, g_st_lo);
    cudaGetSymbolAddress((void**)&f1wH, g_f1w_hi);  cudaGetSymbolAddress((void**)&f1wL, g_f1w_lo);
    cudaGetSymbolAddress((void**)&f1oH, g_f1o_hi);  cudaGetSymbolAddress((void**)&f1oL, g_f1o_lo);
    cudaGetSymbolAddress((void**)&f2wH, g_f2w_hi);  cudaGetSymbolAddress((void**)&f2wL, g_f2w_lo);

    const int SMEM_SZ = 2 * STAGE;
    cudaFuncSetAttribute(mma_gemm_bf, cudaFuncAttributeMaxDynamicSharedMemorySize, SMEM_SZ);
    const int STEP_SMEM = 57856 * 4;   // 231424 B
    cudaFuncSetAttribute(step_loop_kernel, cudaFuncAttributeMaxDynamicSharedMemorySize, STEP_SMEM);

    // weight / input converts
    cvt_pair<<<(8192 * 2048 / 4 + 255) / 256, 256>>>(img, imgH, imgL, 8192 * 2048);
    cvt_pair<<<(2048 * 256 / 4 + 255) / 256, 256>>>(W_fc, wfcH, wfcL, 2048 * 256);
    cvt_pair<<<(256 * 512 / 4 + 255) / 256, 256>>>(W1, w1H, w1L, 256 * 512);
    cvt_pair<<<(256 * 1536 / 4 + 255) / 256, 256>>>(gru_k + 256 * 1536, gk2H, gk2L, 256 * 1536);
    cvt_pair<<<(512 * 512 / 4 + 255) / 256, 256>>>(fc1_w, f1wH, f1wL, 512 * 512);
    cvt_pair<<<(512 * 5000 / 4 + 255) / 256, 256>>>(fc2_w, f2wH, f2wL, 512 * 5000);
    gather_kernel<<<6016, 256>>>(target, emb);

    // encoder: features = relu(img @ W_fc + b_fc); emit fp32 + bf16 pair
    mma_gemm_bf<<<dim3(2, 64), 256, SMEM_SZ>>>(imgH, imgL, wfcH, wfcL, b_fc,
                                               features, featH, featL, 8192, 256, 2048, 1, 0);
    // featw1 = features @ W1 + b1
    mma_gemm_bf<<<dim3(4, 64), 256, SMEM_SZ>>>(featH, featL, w1H, w1L, b1,
                                               featw1, nullptr, nullptr, 8192, 512, 256, 0, 0);
    // embmx = embtok @ gru_k[256:] + gru_b[0]
    mma_gemm_bf<<<dim3(12, 47), 256, SMEM_SZ>>>(etH, etL, gk2H, gk2L, gru_b,
                                                embmx, nullptr, nullptr, 6016, 1536, 256, 0, 0);

    step_loop_kernel<<<128, 256, STEP_SMEM>>>(W2, V, bV, b2, gru_k, gru_b);

    // fc1: states @ fc1_w + fc1_b -> bf16 pair only
    mma_gemm_bf<<<dim3(4, 47), 256, SMEM_SZ>>>(stH, stL, f1wH, f1wL, fc1_b,
                                               nullptr, f1oH, f1oL, 6016, 512, 512, 0, 0);
    // fc2: fc1out @ fc2_w + fc2_b -> out (remapped)
    mma_gemm_bf<<<dim3(40, 47), 256, SMEM_SZ>>>(f1oH, f1oL, f2wH, f2wL, fc2_b,
                                                out, nullptr, nullptr, 6016, 5000, 512, 0, 1);
}

// round 11
// speedup vs baseline: 1.1485x; 1.0780x over previous
#include <cuda_runtime.h>
#include <cuda_bf16.h>
#include <cuda_fp16.h>
#include <cstdint>

#define TS 47

// ---------------- fp32 scratch ----------------
__device__ __align__(128) float g_features[8192 * 256];
__device__ __align__(128) float g_featw1 [8192 * 512];
__device__ __align__(128) float g_embmx  [6016 * 1536];
__device__ __align__(128) float g_hidw2  [2 * 128 * 512];
__device__ __align__(128) float g_context[128 * 256];
__device__ __align__(128) float g_states [6016 * 512];

// ---------------- fp16 planes: A-side hi/lo pairs, B-side single ----------------
__device__ __align__(128) __half g_img_hi [8192 * 2048], g_img_lo [8192 * 2048];
__device__ __align__(128) __half g_feat_hi[8192 * 256],  g_feat_lo[8192 * 256];
__device__ __align__(128) __half g_etok_hi[6016 * 256],  g_etok_lo[6016 * 256];
__device__ __align__(128) __half g_st_hi  [6016 * 512],  g_st_lo  [6016 * 512];
__device__ __align__(128) __half g_f1o_hi [6016 * 512],  g_f1o_lo [6016 * 512];
__device__ __align__(128) __half g_wfc_h [2048 * 256];
__device__ __align__(128) __half g_w1_h  [256 * 512];
__device__ __align__(128) __half g_gk2_h [256 * 1536];
__device__ __align__(128) __half g_f1w_h [512 * 512];
__device__ __align__(128) __half g_f2w_h [512 * 5000];

// ---------------- barrier state (monotonic, replay-safe) ----------------
__device__ unsigned g_flags[128];
__device__ unsigned g_release;
__device__ unsigned g_epoch;

// ---------------- helpers ----------------
__device__ __forceinline__ float tanh_apx(float x) {
    float y;
    asm("tanh.approx.f32 %0, %1;" : "=f"(y) : "f"(x));
    return y;
}
__device__ __forceinline__ unsigned ld_acq(const unsigned* p) {
    unsigned v;
    asm volatile("ld.acquire.gpu.global.u32 %0, [%1];" : "=r"(v) : "l"(p));
    return v;
}
__device__ __forceinline__ void st_rel(unsigned* p, unsigned v) {
    asm volatile("st.release.gpu.global.u32 [%0], %1;" :: "l"(p), "r"(v) : "memory");
}
__device__ __forceinline__ void grid_bar2(int bid, int tid, unsigned tgt) {
    __syncthreads();
    if (bid == 0) {
        if (tid > 0 && tid < 128) {
            while ((int)(ld_acq(&g_flags[tid]) - tgt) < 0) { }
        }
        __syncthreads();
        if (tid == 0) st_rel(&g_release, tgt);
    } else {
        if (tid == 0) {
            st_rel(&g_flags[bid], tgt);
            while ((int)(ld_acq(&g_release) - tgt) < 0) { }
        }
        __syncthreads();
    }
}

__device__ __forceinline__ uint32_t smem_u32(const void* p) {
    uint32_t a;
    asm("{ .reg .u64 t; cvta.to.shared.u64 t, %1; cvt.u32.u64 %0, t; }"
        : "=r"(a) : "l"(p));
    return a;
}
__device__ __forceinline__ void ldsm_x4(uint32_t* r, uint32_t addr) {
    asm volatile("ldmatrix.sync.aligned.m8n8.x4.shared.b16 {%0,%1,%2,%3}, [%4];"
        : "=r"(r[0]), "=r"(r[1]), "=r"(r[2]), "=r"(r[3]) : "r"(addr));
}
__device__ __forceinline__ void ldsm_x2t(uint32_t* r, uint32_t addr) {
    asm volatile("ldmatrix.sync.aligned.m8n8.x2.trans.shared.b16 {%0,%1}, [%2];"
        : "=r"(r[0]), "=r"(r[1]) : "r"(addr));
}
__device__ __forceinline__ void mma_f16(float* c, const uint32_t* a, const uint32_t* b) {
    asm volatile("mma.sync.aligned.m16n8k16.row.col.f32.f16.f16.f32 "
        "{%0,%1,%2,%3},{%4,%5,%6,%7},{%8,%9},{%0,%1,%2,%3};"
        : "+f"(c[0]), "+f"(c[1]), "+f"(c[2]), "+f"(c[3])
        : "r"(a[0]), "r"(a[1]), "r"(a[2]), "r"(a[3]), "r"(b[0]), "r"(b[1]));
}
__device__ __forceinline__ uint32_t packh(__half a, __half b) {
    __half2 t = __halves2half2(a, b);
    return *(uint32_t*)&t;
}
__device__ __forceinline__ void cpasync16(uint32_t sa, const void* ga, int sz) {
    asm volatile("cp.async.cg.shared.global [%0], [%1], 16, %2;"
                 :: "r"(sa), "l"(ga), "r"(sz) : "memory");
}
#define CP_COMMIT() asm volatile("cp.async.commit_group;" ::: "memory")

// ---------------- fp32 -> fp16 hi/lo pair convert (A-side) ----------------
__global__ void cvt_pair_h(const float* __restrict__ s,
                           __half* __restrict__ hi,
                           __half* __restrict__ lo, int n)
{
    int i = (blockIdx.x * 256 + threadIdx.x) * 4;
    if (i >= n) return;
    float4 v = *(const float4*)(s + i);
    __half hx = __float2half(v.x), hy = __float2half(v.y);
    __half hz = __float2half(v.z), hw = __float2half(v.w);
    *(uint2*)(hi + i) = make_uint2(packh(hx, hy), packh(hz, hw));
    __half lx = __float2half(v.x - __half2float(hx));
    __half ly = __float2half(v.y - __half2float(hy));
    __half lz = __float2half(v.z - __half2float(hz));
    __half lw = __float2half(v.w - __half2float(hw));
    *(uint2*)(lo + i) = make_uint2(packh(lx, ly), packh(lz, lw));
}

// ---------------- fp32 -> fp16 single-plane convert (B-side weights) ----------------
__global__ void cvt_one_h(const float* __restrict__ s, __half* __restrict__ h, int n)
{
    int i = (blockIdx.x * 256 + threadIdx.x) * 4;
    if (i >= n) return;
    float4 v = *(const float4*)(s + i);
    *(uint2*)(h + i) = make_uint2(packh(__float2half(v.x), __float2half(v.y)),
                                  packh(__float2half(v.z), __float2half(v.w)));
}

// ---------------- fp16 2-term tensor-core GEMM, cp.async double buffer ----------------
// D = Ahi@B + Alo@B  (dropped Ahi@Blo ~2^-12). 128x128 tile, BK=32, 8 warps.
#define OFF_ALO 10240
#define OFF_B   20480
#define STAGE   29184

__global__ void __launch_bounds__(256, 2) mma_gemm_hf(
    const __half* __restrict__ Ahi, const __half* __restrict__ Alo,
    const __half* __restrict__ B,
    const float* __restrict__ bias, float* __restrict__ C,
    __half* __restrict__ Chi, __half* __restrict__ Clo,
    int M, int N, int K, int relu, int remap)
{
    extern __shared__ char smem[];
    const int tid = threadIdx.x;
    const int wid = tid >> 5, lane = tid & 31;
    const int bm = blockIdx.y * 128, bn = blockIdx.x * 128;
    const int wm = (wid >> 2) * 64;
    const int wn = (wid & 3) * 32;
    const uint32_t sbase = smem_u32(smem);

    float acc[4][4][4] = {};
    const int nc = K >> 5;

    auto issue = [&](int k0, int s) {
        uint32_t sb = sbase + s * STAGE;
        #pragma unroll
        for (int i = 0; i < 2; i++) {
            int task = tid + (i << 8);
            int m = task >> 2, k8 = (task & 3) << 3;
            uint32_t sa = sb + m * 80 + (k8 << 1);
            size_t go = (size_t)(bm + m) * K + k0 + k8;
            cpasync16(sa, Ahi + go, 16);
            cpasync16(sa + OFF_ALO, Alo + go, 16);
        }
        #pragma unroll
        for (int i = 0; i < 2; i++) {
            int task = tid + (i << 8);
            int kk = task >> 4, n8 = (task & 15) << 3;
            int gc = bn + n8;
            uint32_t sa = sb + OFF_B + kk * 272 + (n8 << 1);
            size_t go = (size_t)(k0 + kk) * N + gc;
            int sz = (gc + 8 <= N) ? 16 : 0;
            cpasync16(sa, B + go, sz);
        }
        CP_COMMIT();
    };

    issue(0, 0);

    for (int c = 0; c < nc; c++) {
        int cur = c & 1;
        if (c + 1 < nc) {
            issue((c + 1) << 5, cur ^ 1);
            asm volatile("cp.async.wait_group 1;" ::: "memory");
        } else {
            asm volatile("cp.async.wait_group 0;" ::: "memory");
        }
        __syncthreads();

        uint32_t base = sbase + cur * STAGE;
        uint32_t aAhi = base, aAlo = base + OFF_ALO;
        uint32_t aB = base + OFF_B;

        #pragma unroll
        for (int kk = 0; kk < 2; kk++) {
            int kb = kk * 16;
            uint32_t ahi[4][4], alo[4][4];
            #pragma unroll
            for (int im = 0; im < 4; im++) {
                int row = wm + im * 16 + (lane & 15);
                uint32_t off = row * 80 + kb * 2 + ((lane >> 4) << 4);
                ldsm_x4(ahi[im], aAhi + off);
                ldsm_x4(alo[im], aAlo + off);
            }
            #pragma unroll
            for (int jn = 0; jn < 4; jn++) {
                int n = wn + jn * 8;
                uint32_t off = (kb + (lane & 15)) * 272 + n * 2;
                uint32_t bb[2];
                ldsm_x2t(bb, aB + off);
                #pragma unroll
                for (int im = 0; im < 4; im++) {
                    mma_f16(acc[im][jn], ahi[im], bb);
                    mma_f16(acc[im][jn], alo[im], bb);
                }
            }
        }
        __syncthreads();
    }

    int tr = lane >> 2, tc = (lane & 3) << 1;
    #pragma unroll
    for (int im = 0; im < 4; im++) {
        #pragma unroll
        for (int half = 0; half < 2; half++) {
            int grow = bm + wm + im * 16 + tr + half * 8;
            size_t ro;
            if (remap) {
                int t = grow >> 7, b = grow & 127;
                ro = ((size_t)b * TS + t) * (size_t)N;
            } else {
                ro = (size_t)grow * (size_t)N;
            }
            #pragma unroll
            for (int jn = 0; jn < 4; jn++) {
                int gc = bn + wn + jn * 8 + tc;
                if (gc < N) {
                    float v0 = acc[im][jn][half * 2 + 0] + bias[gc];
                    float v1 = acc[im][jn][half * 2 + 1] + bias[gc + 1];
                    if (relu) { v0 = fmaxf(v0, 0.f); v1 = fmaxf(v1, 0.f); }
                    if (C) *(float2*)(C + ro + gc) = make_float2(v0, v1);
                    if (Chi) {
                        __half h0 = __float2half(v0);
                        __half h1 = __float2half(v1);
                        *(uint32_t*)(Chi + ro + gc) = packh(h0, h1);
                        __half l0 = __float2half(v0 - __half2float(h0));
                        __half l1 = __float2half(v1 - __half2float(h1));
                        *(uint32_t*)(Clo + ro + gc) = packh(l0, l1);
                    }
                }
            }
        }
    }
}

// ---------------- token embedding gather -> fp16 pair ----------------
__global__ void gather_kernel(const int* __restrict__ target,
                              const float* __restrict__ emb)
{
    int row = blockIdx.x;
    int e = threadIdx.x;
    int t = row >> 7, b = row & 127;
    int tok = (t == 0) ? 1 : target[b * 48 + t];
    float v = emb[(size_t)tok * 256 + e];
    __half h = __float2half(v);
    g_etok_hi[(size_t)row * 256 + e] = h;
    g_etok_lo[(size_t)row * 256 + e] = __float2half(v - __half2float(h));
}

// ---------------- persistent step loop (cp.async deep pipelines, R10) ----------------
__global__ __launch_bounds__(256) void step_loop_kernel(
    const float* __restrict__ W2, const float* __restrict__ V,
    const float* __restrict__ bV, const float* __restrict__ b2,
    const float* __restrict__ gru_k, const float* __restrict__ gru_b)
{
    extern __shared__ float dsm[];
    float* sFW1  = dsm;
    float* sFEAT = dsm + 32768;
    float* work  = dsm + 49152;

    const int bid = blockIdx.x;
    const int tid = threadIdx.x;
    unsigned bar = g_epoch;
    const unsigned bar0 = bar;

    for (int j = tid; j < 8192; j += 256)
        *(float4*)&sFW1[j * 4] = *(const float4*)(g_featw1 + (size_t)bid * 32768 + j * 4);
    for (int j = tid; j < 4096; j += 256)
        *(float4*)&sFEAT[j * 4] = *(const float4*)(g_features + (size_t)bid * 16384 + j * 4);
    __syncthreads();

    for (int t = 0; t < TS; t++) {
        // ---- Phase A: hidw2 = states[t-1] @ W2 (K-split 2, 32x32 tiles, 4-stage cp.async) ----
        if (t > 0) {
            int z  = bid >> 6;
            int rr = bid & 63;
            int bm = (rr >> 4) * 32;
            int bn = (rr & 15) * 32;
            const float* A = g_states + (size_t)(t - 1) * 65536;
            float* C = g_hidw2 + z * 65536;
            int kbeg = z * 256;
            int ty = tid >> 4, tx = tid & 15;
            int lrow = tid >> 3, lk4 = (tid & 7) << 2;

            auto issueA = [&](int c) {
                int k0 = kbeg + c * 32;
                uint32_t st = smem_u32(work + (c & 3) * 2048);
                cpasync16(st + (lrow * 32 + lk4) * 4,
                          A + (size_t)(bm + lrow) * 512 + k0 + lk4, 16);
                cpasync16(st + (1024 + lrow * 32 + lk4) * 4,
                          W2 + (size_t)(k0 + lrow) * 512 + bn + lk4, 16);
                CP_COMMIT();
            };
            issueA(0); issueA(1); issueA(2);

            float a00 = 0.f, a01 = 0.f, a10 = 0.f, a11 = 0.f;
            for (int c = 0; c < 8; c++) {
                if (c <= 5)      asm volatile("cp.async.wait_group 2;" ::: "memory");
                else if (c == 6) asm volatile("cp.async.wait_group 1;" ::: "memory");
                else             asm volatile("cp.async.wait_group 0;" ::: "memory");
                __syncthreads();
                const float* As = work + (c & 3) * 2048;
                const float* Bs = As + 1024;
                #pragma unroll
                for (int k = 0; k < 32; k++) {
                    float a0 = As[(ty * 2 + 0) * 32 + k];
                    float a1 = As[(ty * 2 + 1) * 32 + k];
                    float2 b = *(const float2*)&Bs[k * 32 + tx * 2];
                    a00 = fmaf(a0, b.x, a00); a01 = fmaf(a0, b.y, a01);
                    a10 = fmaf(a1, b.x, a10); a11 = fmaf(a1, b.y, a11);
                }
                __syncthreads();
                if (c + 3 < 8) issueA(c + 3);
            }
            int r0 = bm + ty * 2, c0 = bn + tx * 2;
            C[(size_t)(r0 + 0) * 512 + c0 + 0] = a00;
            C[(size_t)(r0 + 0) * 512 + c0 + 1] = a01;
            C[(size_t)(r0 + 1) * 512 + c0 + 0] = a10;
            C[(size_t)(r0 + 1) * 512 + c0 + 1] = a11;
            grid_bar2(bid, tid, ++bar);
        }

        // ---- Phase B: Bahdanau attention ----
        {
            float* hw2 = work;
            float* sV  = work + 512;
            float* sl  = work + 1024;
            int b = bid;
            if (t > 0) {
                hw2[tid]       = g_hidw2[b * 512 + tid]       + g_hidw2[65536 + b * 512 + tid]       + b2[tid];
                hw2[tid + 256] = g_hidw2[b * 512 + tid + 256] + g_hidw2[65536 + b * 512 + tid + 256] + b2[tid + 256];
            } else {
                hw2[tid]       = b2[tid];
                hw2[tid + 256] = b2[tid + 256];
            }
            sV[tid]       = V[tid];
            sV[tid + 256] = V[tid + 256];
            __syncthreads();

            int w = tid >> 5, lane = tid & 31;
            #pragma unroll
            for (int p = 0; p < 8; p++) {
                int l = w * 8 + p;
                const float* row = sFW1 + l * 512;
                float a = 0.f;
                #pragma unroll
                for (int j = 0; j < 16; j++) {
                    int u = lane + j * 32;
                    float s = tanh_apx(row[u] + hw2[u]);
                    a = fmaf(s, sV[u], a);
                }
                #pragma unroll
                for (int o = 16; o; o >>= 1) a += __shfl_xor_sync(0xffffffffu, a, o);
                if (lane == 0) sl[l] = a + bV[0];
            }
            __syncthreads();

            if (tid < 32) {
                float v0 = sl[tid], v1 = sl[tid + 32];
                float m = fmaxf(v0, v1);
                #pragma unroll
                for (int o = 16; o; o >>= 1) m = fmaxf(m, __shfl_xor_sync(0xffffffffu, m, o));
                float e0 = __expf(v0 - m), e1 = __expf(v1 - m);
                float s = e0 + e1;
                #pragma unroll
                for (int o = 16; o; o >>= 1) s += __shfl_xor_sync(0xffffffffu, s, o);
                float inv = 1.0f / s;
                sl[tid] = e0 * inv;
                sl[tid + 32] = e1 * inv;
            }
            __syncthreads();

            float c = 0.f;
            #pragma unroll 8
            for (int l = 0; l < 64; l++)
                c = fmaf(sl[l], sFEAT[l * 256 + tid], c);
            g_context[b * 256 + tid] = c;
        }
        grid_bar2(bid, tid, ++bar);

        // ---- Phase C+D: mx = context @ gru_k[:256] + GRU pointwise (3-stage cp.async) ----
        {
            float* sA = work;
            float* sB = work + 4096;
            int u0 = (bid & 15) * 32;
            int b0 = (bid >> 4) * 16;
            int w = tid >> 5;
            int lane = tid & 31;
            int row0 = 2 * w, row1 = row0 + 1;

            auto issueC = [&](int c) {
                int k0 = c * 16;
                uint32_t st = smem_u32(sB + (c % 3) * 1536);
                #pragma unroll
                for (int i = 0; i < 2; i++) {
                    int idx = tid + (i << 8);
                    if (idx < 384) {
                        int g = idx >> 7, rem = idx & 127;
                        int k = rem >> 3, u4 = (rem & 7) << 2;
                        cpasync16(st + (g * 512 + k * 32 + u4) * 4,
                                  gru_k + (size_t)(k0 + k) * 1536 + g * 512 + u0 + u4, 16);
                    }
                }
            };
            {
                uint32_t stA = smem_u32(sA);
                #pragma unroll
                for (int i = 0; i < 4; i++) {
                    int f = tid + (i << 8);
                    int row = f >> 6, q = f & 63;
                    cpasync16(stA + (row * 256 + q * 4) * 4,
                              g_context + (size_t)(b0 + row) * 256 + q * 4, 16);
                }
                issueC(0);
                CP_COMMIT();
            }
            issueC(1); CP_COMMIT();

            float az0 = 0.f, ar0 = 0.f, ah0 = 0.f;
            float az1 = 0.f, ar1 = 0.f, ah1 = 0.f;

            for (int c = 0; c < 16; c++) {
                if (c < 15) asm volatile("cp.async.wait_group 1;" ::: "memory");
                else        asm volatile("cp.async.wait_group 0;" ::: "memory");
                __syncthreads();
                const float* Bs = sB + (c % 3) * 1536;
                int kb = c * 16;
                #pragma unroll
                for (int k = 0; k < 16; k++) {
                    float bz = Bs[k * 32 + lane];
                    float br = Bs[512 + k * 32 + lane];
                    float bh = Bs[1024 + k * 32 + lane];
                    float a0 = sA[row0 * 256 + kb + k];
                    float a1 = sA[row1 * 256 + kb + k];
                    az0 = fmaf(a0, bz, az0); ar0 = fmaf(a0, br, ar0); ah0 = fmaf(a0, bh, ah0);
                    az1 = fmaf(a1, bz, az1); ar1 = fmaf(a1, br, ar1); ah1 = fmaf(a1, bh, ah1);
                }
                __syncthreads();
                if (c + 2 < 16) { issueC(c + 2); CP_COMMIT(); }
            }

            int u = u0 + lane;
            float rz = gru_b[1536 + u];
            float rr = gru_b[2048 + u];
            float rh = gru_b[2560 + u];
            #pragma unroll
            for (int i = 0; i < 2; i++) {
                int b = b0 + row0 + i;
                size_t r = (size_t)t * 128 + b;
                float xz = (i ? az1 : az0) + g_embmx[r * 1536 + u];
                float xr = (i ? ar1 : ar0) + g_embmx[r * 1536 + 512 + u];
                float xh = (i ? ah1 : ah0) + g_embmx[r * 1536 + 1024 + u];
                float z  = 1.f / (1.f + __expf(-(xz + rz)));
                float rg = 1.f / (1.f + __expf(-(xr + rr)));
                float hh = tanh_apx(xh + rg * rh);
                float st = (1.f - z) * hh;
                g_states[r * 512 + u] = st;
                __half h = __float2half(st);
                g_st_hi[r * 512 + u] = h;
                g_st_lo[r * 512 + u] = __float2half(st - __half2float(h));
            }
        }
        grid_bar2(bid, tid, ++bar);
    }

    if (bid == 0 && tid == 0) g_epoch = bar0 + (unsigned)(3 * TS - 1);
}

// ---------------- launch ----------------
extern "C" void kernel_launch(void* const* d_in, const int* in_sizes, int n_in,
                              void* d_out, int out_size)
{
    const float* img    = (const float*)d_in[0];
    const int*   target = (const int*)  d_in[1];
    const float* W_fc   = (const float*)d_in[2];
    const float* b_fc   = (const float*)d_in[3];
    const float* W1     = (const float*)d_in[4];
    const float* b1     = (const float*)d_in[5];
    const float* W2     = (const float*)d_in[6];
    const float* b2     = (const float*)d_in[7];
    const float* V      = (const float*)d_in[8];
    const float* bV     = (const float*)d_in[9];
    const float* emb    = (const float*)d_in[10];
    const float* gru_k  = (const float*)d_in[11];
    /* d_in[12] = gru_rk : dead (zero GRU state) */
    const float* gru_b  = (const float*)d_in[13];
    const float* fc1_w  = (const float*)d_in[14];
    const float* fc1_b  = (const float*)d_in[15];
    const float* fc2_w  = (const float*)d_in[16];
    const float* fc2_b  = (const float*)d_in[17];
    float* out = (float*)d_out;

    float *features, *featw1, *embmx;
    __half *imgH, *imgL, *featH, *featL, *etH, *etL, *stH, *stL, *f1oH, *f1oL;
    __half *wfcH, *w1H, *gk2H, *f1wH, *f2wH;
    cudaGetSymbolAddress((void**)&features, g_features);
    cudaGetSymbolAddress((void**)&featw1,  g_featw1);
    cudaGetSymbolAddress((void**)&embmx,   g_embmx);
    cudaGetSymbolAddress((void**)&imgH, g_img_hi);   cudaGetSymbolAddress((void**)&imgL, g_img_lo);
    cudaGetSymbolAddress((void**)&featH, g_feat_hi); cudaGetSymbolAddress((void**)&featL, g_feat_lo);
    cudaGetSymbolAddress((void**)&etH, g_etok_hi);   cudaGetSymbolAddress((void**)&etL, g_etok_lo);
    cudaGetSymbolAddress((void**)&stH, g_st_hi);     cudaGetSymbolAddress((void**)&stL, g_st_lo);
    cudaGetSymbolAddress((void**)&f1oH, g_f1o_hi);   cudaGetSymbolAddress((void**)&f1oL, g_f1o_lo);
    cudaGetSymbolAddress((void**)&wfcH, g_wfc_h);
    cudaGetSymbolAddress((void**)&w1H,  g_w1_h);
    cudaGetSymbolAddress((void**)&gk2H, g_gk2_h);
    cudaGetSymbolAddress((void**)&f1wH, g_f1w_h);
    cudaGetSymbolAddress((void**)&f2wH, g_f2w_h);

    const int SMEM_SZ = 2 * STAGE;
    cudaFuncSetAttribute(mma_gemm_hf, cudaFuncAttributeMaxDynamicSharedMemorySize, SMEM_SZ);
    const int STEP_SMEM = 57856 * 4;   // 231424 B
    cudaFuncSetAttribute(step_loop_kernel, cudaFuncAttributeMaxDynamicSharedMemorySize, STEP_SMEM);

    // converts + gather
    cvt_pair_h<<<(8192 * 2048 / 4 + 255) / 256, 256>>>(img, imgH, imgL, 8192 * 2048);
    cvt_one_h<<<(2048 * 256 / 4 + 255) / 256, 256>>>(W_fc, wfcH, 2048 * 256);
    cvt_one_h<<<(256 * 512 / 4 + 255) / 256, 256>>>(W1, w1H, 256 * 512);
    cvt_one_h<<<(256 * 1536 / 4 + 255) / 256, 256>>>(gru_k + 256 * 1536, gk2H, 256 * 1536);
    cvt_one_h<<<(512 * 512 / 4 + 255) / 256, 256>>>(fc1_w, f1wH, 512 * 512);
    cvt_one_h<<<(512 * 5000 / 4 + 255) / 256, 256>>>(fc2_w, f2wH, 512 * 5000);
    gather_kernel<<<6016, 256>>>(target, emb);

    // encoder: features = relu(img @ W_fc + b_fc); emit fp32 + fp16 pair
    mma_gemm_hf<<<dim3(2, 64), 256, SMEM_SZ>>>(imgH, imgL, wfcH, b_fc,
                                               features, featH, featL, 8192, 256, 2048, 1, 0);
    // featw1 = features @ W1 + b1
    mma_gemm_hf<<<dim3(4, 64), 256, SMEM_SZ>>>(featH, featL, w1H, b1,
                                               featw1, nullptr, nullptr, 8192, 512, 256, 0, 0);
    // embmx = embtok @ gru_k[256:] + gru_b[0]
    mma_gemm_hf<<<dim3(12, 47), 256, SMEM_SZ>>>(etH, etL, gk2H, gru_b,
                                                embmx, nullptr, nullptr, 6016, 1536, 256, 0, 0);

    step_loop_kernel<<<128, 256, STEP_SMEM>>>(W2, V, bV, b2, gru_k, gru_b);

    // fc1: states @ fc1_w + fc1_b -> fp16 pair
    mma_gemm_hf<<<dim3(4, 47), 256, SMEM_SZ>>>(stH, stL, f1wH, fc1_b,
                                               nullptr, f1oH, f1oL, 6016, 512, 512, 0, 0);
    // fc2: fc1out @ fc2_w + fc2_b -> out (remapped)
    mma_gemm_hf<<<dim3(40, 47), 256, SMEM_SZ>>>(f1oH, f1oL, f2wH, fc2_b,
                                                out, nullptr, nullptr, 6016, 5000, 512, 0, 1);
}

// round 12
// speedup vs baseline: 1.4365x; 1.2507x over previous
#include <cuda_runtime.h>
#include <cuda_fp16.h>
#include <cstdint>

#define TS 47

// ---------------- fp32 scratch ----------------
__device__ __align__(128) float g_featw1 [8192 * 512];
__device__ __align__(128) float g_features[8192 * 256];
__device__ __align__(128) float g_embmx  [6016 * 1536];
__device__ __align__(128) float g_hidw2  [128 * 512];

// ---------------- fp16 planes ----------------
__device__ __align__(128) __half g_img_hi [8192 * 2048], g_img_lo [8192 * 2048];
__device__ __align__(128) __half g_feat_hi[8192 * 256],  g_feat_lo[8192 * 256];
__device__ __align__(128) __half g_etok_hi[6016 * 256],  g_etok_lo[6016 * 256];
__device__ __align__(128) __half g_st_hi  [6016 * 512],  g_st_lo  [6016 * 512];
__device__ __align__(128) __half g_f1o_hi [6016 * 512],  g_f1o_lo [6016 * 512];
__device__ __align__(128) __half g_ctx_hi [128 * 256],   g_ctx_lo [128 * 256];
__device__ __align__(128) __half g_wfc_h [2048 * 256];
__device__ __align__(128) __half g_w1_h  [256 * 512];
__device__ __align__(128) __half g_gk1_h [256 * 1536];
__device__ __align__(128) __half g_gk2_h [256 * 1536];
__device__ __align__(128) __half g_w2_h  [512 * 512];
__device__ __align__(128) __half g_f1w_h [512 * 512];
__device__ __align__(128) __half g_f2w_h [512 * 5000];

// ---------------- barrier state (monotonic, replay-safe) ----------------
__device__ unsigned g_flags[128];
__device__ unsigned g_release;
__device__ unsigned g_epoch;

// ---------------- helpers ----------------
__device__ __forceinline__ float tanh_apx(float x) {
    float y;
    asm("tanh.approx.f32 %0, %1;" : "=f"(y) : "f"(x));
    return y;
}
__device__ __forceinline__ unsigned ld_acq(const unsigned* p) {
    unsigned v;
    asm volatile("ld.acquire.gpu.global.u32 %0, [%1];" : "=r"(v) : "l"(p));
    return v;
}
__device__ __forceinline__ void st_rel(unsigned* p, unsigned v) {
    asm volatile("st.release.gpu.global.u32 [%0], %1;" :: "l"(p), "r"(v) : "memory");
}
__device__ __forceinline__ void grid_bar2(int bid, int tid, unsigned tgt) {
    __syncthreads();
    if (bid == 0) {
        if (tid > 0 && tid < 128) {
            while ((int)(ld_acq(&g_flags[tid]) - tgt) < 0) { }
        }
        __syncthreads();
        if (tid == 0) st_rel(&g_release, tgt);
    } else {
        if (tid == 0) {
            st_rel(&g_flags[bid], tgt);
            while ((int)(ld_acq(&g_release) - tgt) < 0) { }
        }
        __syncthreads();
    }
}
__device__ __forceinline__ uint32_t smem_u32(const void* p) {
    uint32_t a;
    asm("{ .reg .u64 t; cvta.to.shared.u64 t, %1; cvt.u32.u64 %0, t; }"
        : "=r"(a) : "l"(p));
    return a;
}
__device__ __forceinline__ void ldsm_x4(uint32_t* r, uint32_t addr) {
    asm volatile("ldmatrix.sync.aligned.m8n8.x4.shared.b16 {%0,%1,%2,%3}, [%4];"
        : "=r"(r[0]), "=r"(r[1]), "=r"(r[2]), "=r"(r[3]) : "r"(addr));
}
__device__ __forceinline__ void ldsm_x2t(uint32_t* r, uint32_t addr) {
    asm volatile("ldmatrix.sync.aligned.m8n8.x2.trans.shared.b16 {%0,%1}, [%2];"
        : "=r"(r[0]), "=r"(r[1]) : "r"(addr));
}
__device__ __forceinline__ void mma_f16(float* c, const uint32_t* a, const uint32_t* b) {
    asm volatile("mma.sync.aligned.m16n8k16.row.col.f32.f16.f16.f32 "
        "{%0,%1,%2,%3},{%4,%5,%6,%7},{%8,%9},{%0,%1,%2,%3};"
        : "+f"(c[0]), "+f"(c[1]), "+f"(c[2]), "+f"(c[3])
        : "r"(a[0]), "r"(a[1]), "r"(a[2]), "r"(a[3]), "r"(b[0]), "r"(b[1]));
}
__device__ __forceinline__ uint32_t packh(__half a, __half b) {
    __half2 t = __halves2half2(a, b);
    return *(uint32_t*)&t;
}
__device__ __forceinline__ void cpasync16(uint32_t sa, const void* ga, int sz) {
    asm volatile("cp.async.cg.shared.global [%0], [%1], 16, %2;"
                 :: "r"(sa), "l"(ga), "r"(sz) : "memory");
}
#define CP_COMMIT() asm volatile("cp.async.commit_group;" ::: "memory")

// ---------------- fused fp32 -> fp16 converts (ONE launch) ----------------
// block ranges: img pair [0,16384) | wfc [,16896) | w1 [,17024) | gk2 [,17408)
//               f1w [,17664) | f2w [,20164) | w2 [,20420) | gk1 [,20804)
__global__ void cvt_fused(const float* __restrict__ img, const float* __restrict__ W_fc,
                          const float* __restrict__ W1, const float* __restrict__ gru_k,
                          const float* __restrict__ fc1_w, const float* __restrict__ fc2_w,
                          const float* __restrict__ W2)
{
    int blk = blockIdx.x;
    const float* src;
    __half *hi = nullptr, *lo = nullptr, *one = nullptr;
    int base;
    if (blk < 16384)      { src = img;              hi = g_img_hi; lo = g_img_lo; base = blk; }
    else if (blk < 16896) { src = W_fc;             one = g_wfc_h; base = blk - 16384; }
    else if (blk < 17024) { src = W1;               one = g_w1_h;  base = blk - 16896; }
    else if (blk < 17408) { src = gru_k + 256*1536; one = g_gk2_h; base = blk - 17024; }
    else if (blk < 17664) { src = fc1_w;            one = g_f1w_h; base = blk - 17408; }
    else if (blk < 20164) { src = fc2_w;            one = g_f2w_h; base = blk - 17664; }
    else if (blk < 20420) { src = W2;               one = g_w2_h;  base = blk - 20164; }
    else                  { src = gru_k;            one = g_gk1_h; base = blk - 20420; }
    int i = (base * 256 + threadIdx.x) * 4;
    float4 v = *(const float4*)(src + i);
    __half hx = __float2half(v.x), hy = __float2half(v.y);
    __half hz = __float2half(v.z), hw = __float2half(v.w);
    if (one) {
        *(uint2*)(one + i) = make_uint2(packh(hx, hy), packh(hz, hw));
    } else {
        *(uint2*)(hi + i) = make_uint2(packh(hx, hy), packh(hz, hw));
        __half lx = __float2half(v.x - __half2float(hx));
        __half ly = __float2half(v.y - __half2float(hy));
        __half lz = __float2half(v.z - __half2float(hz));
        __half lw = __float2half(v.w - __half2float(hw));
        *(uint2*)(lo + i) = make_uint2(packh(lx, ly), packh(lz, lw));
    }
}

// ---------------- fp16 2-term tensor-core GEMM (R11, unchanged) ----------------
#define OFF_ALO 10240
#define OFF_B   20480
#define STAGE   29184

__global__ void __launch_bounds__(256, 2) mma_gemm_hf(
    const __half* __restrict__ Ahi, const __half* __restrict__ Alo,
    const __half* __restrict__ B,
    const float* __restrict__ bias, float* __restrict__ C,
    __half* __restrict__ Chi, __half* __restrict__ Clo,
    int M, int N, int K, int relu, int remap)
{
    extern __shared__ char smem[];
    const int tid = threadIdx.x;
    const int wid = tid >> 5, lane = tid & 31;
    const int bm = blockIdx.y * 128, bn = blockIdx.x * 128;
    const int wm = (wid >> 2) * 64;
    const int wn = (wid & 3) * 32;
    const uint32_t sbase = smem_u32(smem);

    float acc[4][4][4] = {};
    const int nc = K >> 5;

    auto issue = [&](int k0, int s) {
        uint32_t sb = sbase + s * STAGE;
        #pragma unroll
        for (int i = 0; i < 2; i++) {
            int task = tid + (i << 8);
            int m = task >> 2, k8 = (task & 3) << 3;
            uint32_t sa = sb + m * 80 + (k8 << 1);
            size_t go = (size_t)(bm + m) * K + k0 + k8;
            cpasync16(sa, Ahi + go, 16);
            cpasync16(sa + OFF_ALO, Alo + go, 16);
        }
        #pragma unroll
        for (int i = 0; i < 2; i++) {
            int task = tid + (i << 8);
            int kk = task >> 4, n8 = (task & 15) << 3;
            int gc = bn + n8;
            uint32_t sa = sb + OFF_B + kk * 272 + (n8 << 1);
            size_t go = (size_t)(k0 + kk) * N + gc;
            int sz = (gc + 8 <= N) ? 16 : 0;
            cpasync16(sa, B + go, sz);
        }
        CP_COMMIT();
    };

    issue(0, 0);

    for (int c = 0; c < nc; c++) {
        int cur = c & 1;
        if (c + 1 < nc) {
            issue((c + 1) << 5, cur ^ 1);
            asm volatile("cp.async.wait_group 1;" ::: "memory");
        } else {
            asm volatile("cp.async.wait_group 0;" ::: "memory");
        }
        __syncthreads();

        uint32_t base = sbase + cur * STAGE;
        uint32_t aAhi = base, aAlo = base + OFF_ALO;
        uint32_t aB = base + OFF_B;

        #pragma unroll
        for (int kk = 0; kk < 2; kk++) {
            int kb = kk * 16;
            uint32_t ahi[4][4], alo[4][4];
            #pragma unroll
            for (int im = 0; im < 4; im++) {
                int row = wm + im * 16 + (lane & 15);
                uint32_t off = row * 80 + kb * 2 + ((lane >> 4) << 4);
                ldsm_x4(ahi[im], aAhi + off);
                ldsm_x4(alo[im], aAlo + off);
            }
            #pragma unroll
            for (int jn = 0; jn < 4; jn++) {
                int n = wn + jn * 8;
                uint32_t off = (kb + (lane & 15)) * 272 + n * 2;
                uint32_t bb[2];
                ldsm_x2t(bb, aB + off);
                #pragma unroll
                for (int im = 0; im < 4; im++) {
                    mma_f16(acc[im][jn], ahi[im], bb);
                    mma_f16(acc[im][jn], alo[im], bb);
                }
            }
        }
        __syncthreads();
    }

    int tr = lane >> 2, tc = (lane & 3) << 1;
    #pragma unroll
    for (int im = 0; im < 4; im++) {
        #pragma unroll
        for (int half = 0; half < 2; half++) {
            int grow = bm + wm + im * 16 + tr + half * 8;
            size_t ro;
            if (remap) {
                int t = grow >> 7, b = grow & 127;
                ro = ((size_t)b * TS + t) * (size_t)N;
            } else {
                ro = (size_t)grow * (size_t)N;
            }
            #pragma unroll
            for (int jn = 0; jn < 4; jn++) {
                int gc = bn + wn + jn * 8 + tc;
                if (gc < N) {
                    float v0 = acc[im][jn][half * 2 + 0] + bias[gc];
                    float v1 = acc[im][jn][half * 2 + 1] + bias[gc + 1];
                    if (relu) { v0 = fmaxf(v0, 0.f); v1 = fmaxf(v1, 0.f); }
                    if (C) *(float2*)(C + ro + gc) = make_float2(v0, v1);
                    if (Chi) {
                        __half h0 = __float2half(v0);
                        __half h1 = __float2half(v1);
                        *(uint32_t*)(Chi + ro + gc) = packh(h0, h1);
                        __half l0 = __float2half(v0 - __half2float(h0));
                        __half l1 = __float2half(v1 - __half2float(h1));
                        *(uint32_t*)(Clo + ro + gc) = packh(l0, l1);
                    }
                }
            }
        }
    }
}

// ---------------- token embedding gather -> fp16 pair ----------------
__global__ void gather_kernel(const int* __restrict__ target,
                              const float* __restrict__ emb)
{
    int row = blockIdx.x;
    int e = threadIdx.x;
    int t = row >> 7, b = row & 127;
    int tok = (t == 0) ? 1 : target[b * 48 + t];
    float v = emb[(size_t)tok * 256 + e];
    __half h = __float2half(v);
    g_etok_hi[(size_t)row * 256 + e] = h;
    g_etok_lo[(size_t)row * 256 + e] = __float2half(v - __half2float(h));
}

// ---------------- persistent step loop: tensor-core phases A & C ----------------
// dyn smem (floats): sFW1 [0..32767], sFEAT [32768..49151], work [49152..56703]
// Phase A work (bytes from work): Ahi 32x144B @0, Alo @4608, W2 64x80B @9216; stage 14336 x2
// Phase C work: ctxHi 16x528B @0, ctxLo @8448, W stages @16896 (32x208B=6656 x2)
__global__ __launch_bounds__(256) void step_loop_kernel(
    const float* __restrict__ V, const float* __restrict__ bV,
    const float* __restrict__ b2, const float* __restrict__ gru_b)
{
    extern __shared__ float dsm[];
    float* sFW1  = dsm;
    float* sFEAT = dsm + 32768;
    float* work  = dsm + 49152;

    const int bid = blockIdx.x;
    const int tid = threadIdx.x;
    const int wid = tid >> 5, lane = tid & 31;
    unsigned bar = g_epoch;
    const unsigned bar0 = bar;

    for (int j = tid; j < 8192; j += 256)
        *(float4*)&sFW1[j * 4] = *(const float4*)(g_featw1 + (size_t)bid * 32768 + j * 4);
    for (int j = tid; j < 4096; j += 256)
        *(float4*)&sFEAT[j * 4] = *(const float4*)(g_features + (size_t)bid * 16384 + j * 4);
    __syncthreads();

    const uint32_t wb = smem_u32(work);

    for (int t = 0; t < TS; t++) {
        // ---- Phase A: hidw2 = states[t-1] @ W2, fp16 2-term mma (64 blocks, 32x32 tiles) ----
        if (t > 0) {
            if (bid < 64) {
                int bm = (bid >> 4) * 32, bn = (bid & 15) * 32;
                const __half* Ah = g_st_hi + (size_t)(t - 1) * 65536;
                const __half* Al = g_st_lo + (size_t)(t - 1) * 65536;

                auto issueA = [&](int c) {
                    uint32_t st = wb + (c & 1) * 14336;
                    int k0 = c * 64;
                    #pragma unroll
                    for (int i = 0; i < 2; i++) {
                        int idx = tid + (i << 8);
                        int r = idx >> 4, rem = idx & 15, pl = rem >> 3, seg = rem & 7;
                        const __half* src = (pl ? Al : Ah) + (size_t)(bm + r) * 512 + k0 + seg * 8;
                        cpasync16(st + pl * 4608 + r * 144 + seg * 16, src, 16);
                    }
                    {
                        int kr = tid >> 2, seg = tid & 3;
                        cpasync16(st + 9216 + kr * 80 + seg * 16,
                                  g_w2_h + (size_t)(k0 + kr) * 512 + bn + seg * 8, 16);
                    }
                    CP_COMMIT();
                };
                issueA(0); issueA(1);

                int wmi = (wid >> 2) * 16;
                int wni = (wid & 3) * 8;
                float acc[4] = {};
                for (int c = 0; c < 8; c++) {
                    if (c < 7) asm volatile("cp.async.wait_group 1;" ::: "memory");
                    else       asm volatile("cp.async.wait_group 0;" ::: "memory");
                    __syncthreads();
                    uint32_t st = wb + (c & 1) * 14336;
                    #pragma unroll
                    for (int ks = 0; ks < 4; ks++) {
                        uint32_t ahi[4], alo[4], bb[2];
                        int row = wmi + (lane & 15);
                        uint32_t aoff = row * 144 + ks * 32 + ((lane >> 4) << 4);
                        ldsm_x4(ahi, st + aoff);
                        ldsm_x4(alo, st + 4608 + aoff);
                        uint32_t boff = 9216 + (ks * 16 + (lane & 15)) * 80 + wni * 2;
                        ldsm_x2t(bb, st + boff);
                        mma_f16(acc, ahi, bb);
                        mma_f16(acc, alo, bb);
                    }
                    __syncthreads();
                    if (c + 2 < 8) issueA(c + 2);
                }
                int tr = lane >> 2, tc2 = (lane & 3) * 2;
                int col = bn + wni + tc2;
                *(float2*)&g_hidw2[(bm + wmi + tr) * 512 + col] = make_float2(acc[0], acc[1]);
                *(float2*)&g_hidw2[(bm + wmi + tr + 8) * 512 + col] = make_float2(acc[2], acc[3]);
            }
            grid_bar2(bid, tid, ++bar);
        }

        // ---- Phase B: Bahdanau attention (smem featw1/features); emits ctx fp16 pairs ----
        {
            float* hw2 = work;
            float* sV  = work + 512;
            float* sl  = work + 1024;
            int b = bid;
            if (t > 0) {
                hw2[tid]       = g_hidw2[b * 512 + tid]       + b2[tid];
                hw2[tid + 256] = g_hidw2[b * 512 + tid + 256] + b2[tid + 256];
            } else {
                hw2[tid]       = b2[tid];
                hw2[tid + 256] = b2[tid + 256];
            }
            sV[tid]       = V[tid];
            sV[tid + 256] = V[tid + 256];
            __syncthreads();

            #pragma unroll
            for (int p = 0; p < 8; p++) {
                int l = wid * 8 + p;
                const float* row = sFW1 + l * 512;
                float a = 0.f;
                #pragma unroll
                for (int j = 0; j < 16; j++) {
                    int u = lane + j * 32;
                    float s = tanh_apx(row[u] + hw2[u]);
                    a = fmaf(s, sV[u], a);
                }
                #pragma unroll
                for (int o = 16; o; o >>= 1) a += __shfl_xor_sync(0xffffffffu, a, o);
                if (lane == 0) sl[l] = a + bV[0];
            }
            __syncthreads();

            if (tid < 32) {
                float v0 = sl[tid], v1 = sl[tid + 32];
                float m = fmaxf(v0, v1);
                #pragma unroll
                for (int o = 16; o; o >>= 1) m = fmaxf(m, __shfl_xor_sync(0xffffffffu, m, o));
                float e0 = __expf(v0 - m), e1 = __expf(v1 - m);
                float s = e0 + e1;
                #pragma unroll
                for (int o = 16; o; o >>= 1) s += __shfl_xor_sync(0xffffffffu, s, o);
                float inv = 1.0f / s;
                sl[tid] = e0 * inv;
                sl[tid + 32] = e1 * inv;
            }
            __syncthreads();

            float c = 0.f;
            #pragma unroll 8
            for (int l = 0; l < 64; l++)
                c = fmaf(sl[l], sFEAT[l * 256 + tid], c);
            __half h = __float2half(c);
            g_ctx_hi[b * 256 + tid] = h;
            g_ctx_lo[b * 256 + tid] = __float2half(c - __half2float(h));
        }
        grid_bar2(bid, tid, ++bar);

        // ---- Phase C+D: mx = ctx @ gru_k[:256] (fp16 mma) + GRU pointwise ----
        {
            int b0 = (bid >> 4) * 16;
            int u0 = (bid & 15) * 32;
            const uint32_t CTXLO = 8448, WST = 16896, WSZ = 6656;

            auto issueW = [&](int c) {
                uint32_t st = wb + WST + (c & 1) * WSZ;
                int k0 = c * 32;
                #pragma unroll
                for (int i = 0; i < 2; i++) {
                    int idx = tid + (i << 8);
                    if (idx < 384) {
                        int g = idx >> 7, rem = idx & 127, kr = rem >> 2, seg = rem & 3;
                        cpasync16(st + kr * 208 + g * 64 + seg * 16,
                                  g_gk1_h + (size_t)(k0 + kr) * 1536 + g * 512 + u0 + seg * 8, 16);
                    }
                }
            };
            {
                #pragma unroll
                for (int i = 0; i < 4; i++) {
                    int idx = tid + (i << 8);
                    int r = idx >> 6, rem = idx & 63, pl = rem >> 5, seg = rem & 31;
                    const __half* src = (pl ? g_ctx_lo : g_ctx_hi) + (size_t)(b0 + r) * 256 + seg * 8;
                    cpasync16(wb + pl * CTXLO + r * 528 + seg * 16, src, 16);
                }
                issueW(0); CP_COMMIT();
                issueW(1); CP_COMMIT();
            }

            float acc0[4] = {}, acc1[4] = {};
            int tile0 = wid, tile1 = wid + 8;

            for (int c = 0; c < 8; c++) {
                if (c < 7) asm volatile("cp.async.wait_group 1;" ::: "memory");
                else       asm volatile("cp.async.wait_group 0;" ::: "memory");
                __syncthreads();
                uint32_t st = wb + WST + (c & 1) * WSZ;
                #pragma unroll
                for (int ks = 0; ks < 2; ks++) {
                    uint32_t ahi[4], alo[4], bb[2];
                    int row = lane & 15;
                    uint32_t aoff = row * 528 + (c * 32 + ks * 16) * 2 + ((lane >> 4) << 4);
                    ldsm_x4(ahi, wb + aoff);
                    ldsm_x4(alo, wb + CTXLO + aoff);
                    {
                        int g = tile0 >> 2, ns = tile0 & 3;
                        ldsm_x2t(bb, st + (ks * 16 + (lane & 15)) * 208 + g * 64 + ns * 16);
                        mma_f16(acc0, ahi, bb);
                        mma_f16(acc0, alo, bb);
                    }
                    if (wid < 4) {
                        int g = tile1 >> 2, ns = tile1 & 3;
                        ldsm_x2t(bb, st + (ks * 16 + (lane & 15)) * 208 + g * 64 + ns * 16);
                        mma_f16(acc1, ahi, bb);
                        mma_f16(acc1, alo, bb);
                    }
                }
                __syncthreads();
                if (c + 2 < 8) { issueW(c + 2); CP_COMMIT(); }
            }

            // fragments -> smem mx (16 x 104), then fused GRU pointwise
            __syncthreads();
            float* mxs = work;
            int tr = lane >> 2, tc2 = (lane & 3) * 2;
            {
                int cb = (tile0 >> 2) * 32 + (tile0 & 3) * 8 + tc2;
                mxs[tr * 104 + cb] = acc0[0];       mxs[tr * 104 + cb + 1] = acc0[1];
                mxs[(tr + 8) * 104 + cb] = acc0[2]; mxs[(tr + 8) * 104 + cb + 1] = acc0[3];
            }
            if (wid < 4) {
                int cb = (tile1 >> 2) * 32 + (tile1 & 3) * 8 + tc2;
                mxs[tr * 104 + cb] = acc1[0];       mxs[tr * 104 + cb + 1] = acc1[1];
                mxs[(tr + 8) * 104 + cb] = acc1[2]; mxs[(tr + 8) * 104 + cb + 1] = acc1[3];
            }
            __syncthreads();

            #pragma unroll
            for (int i = 0; i < 2; i++) {
                int it = tid + (i << 8);
                int ul = it & 31, b = it >> 5;
                int u = u0 + ul;
                size_t r = (size_t)t * 128 + (b0 + b);
                float xz = mxs[b * 104 + ul]      + g_embmx[r * 1536 + u];
                float xr = mxs[b * 104 + 32 + ul] + g_embmx[r * 1536 + 512 + u];
                float xh = mxs[b * 104 + 64 + ul] + g_embmx[r * 1536 + 1024 + u];
                float rz = gru_b[1536 + u];
                float rr = gru_b[2048 + u];
                float rh = gru_b[2560 + u];
                float z  = 1.f / (1.f + __expf(-(xz + rz)));
                float rg = 1.f / (1.f + __expf(-(xr + rr)));
                float hh = tanh_apx(xh + rg * rh);
                float st = (1.f - z) * hh;
                __half h = __float2half(st);
                g_st_hi[r * 512 + u] = h;
                g_st_lo[r * 512 + u] = __float2half(st - __half2float(h));
            }
        }
        grid_bar2(bid, tid, ++bar);
    }

    if (bid == 0 && tid == 0) g_epoch = bar0 + (unsigned)(3 * TS - 1);
}

// ---------------- launch ----------------
extern "C" void kernel_launch(void* const* d_in, const int* in_sizes, int n_in,
                              void* d_out, int out_size)
{
    const float* img    = (const float*)d_in[0];
    const int*   target = (const int*)  d_in[1];
    const float* W_fc   = (const float*)d_in[2];
    const float* b_fc   = (const float*)d_in[3];
    const float* W1     = (const float*)d_in[4];
    const float* b1     = (const float*)d_in[5];
    const float* W2     = (const float*)d_in[6];
    const float* b2     = (const float*)d_in[7];
    const float* V      = (const float*)d_in[8];
    const float* bV     = (const float*)d_in[9];
    const float* emb    = (const float*)d_in[10];
    const float* gru_k  = (const float*)d_in[11];
    /* d_in[12] = gru_rk : dead (zero GRU state) */
    const float* gru_b  = (const float*)d_in[13];
    const float* fc1_w  = (const float*)d_in[14];
    const float* fc1_b  = (const float*)d_in[15];
    const float* fc2_w  = (const float*)d_in[16];
    const float* fc2_b  = (const float*)d_in[17];
    float* out = (float*)d_out;

    float *featw1, *features, *embmx;
    __half *imgH, *imgL, *featH, *featL, *etH, *etL, *stH, *stL, *f1oH, *f1oL;
    __half *wfcH, *w1H, *gk2H, *f1wH, *f2wH;
    cudaGetSymbolAddress((void**)&featw1,   g_featw1);
    cudaGetSymbolAddress((void**)&features, g_features);
    cudaGetSymbolAddress((void**)&embmx,    g_embmx);
    cudaGetSymbolAddress((void**)&imgH, g_img_hi);   cudaGetSymbolAddress((void**)&imgL, g_img_lo);
    cudaGetSymbolAddress((void**)&featH, g_feat_hi); cudaGetSymbolAddress((void**)&featL, g_feat_lo);
    cudaGetSymbolAddress((void**)&etH, g_etok_hi);   cudaGetSymbolAddress((void**)&etL, g_etok_lo);
    cudaGetSymbolAddress((void**)&stH, g_st_hi);     cudaGetSymbolAddress((void**)&stL, g_st_lo);
    cudaGetSymbolAddress((void**)&f1oH, g_f1o_hi);   cudaGetSymbolAddress((void**)&f1oL, g_f1o_lo);
    cudaGetSymbolAddress((void**)&wfcH, g_wfc_h);
    cudaGetSymbolAddress((void**)&w1H,  g_w1_h);
    cudaGetSymbolAddress((void**)&gk2H, g_gk2_h);
    cudaGetSymbolAddress((void**)&f1wH, g_f1w_h);
    cudaGetSymbolAddress((void**)&f2wH, g_f2w_h);

    const int SMEM_SZ = 2 * STAGE;
    cudaFuncSetAttribute(mma_gemm_hf, cudaFuncAttributeMaxDynamicSharedMemorySize, SMEM_SZ);
    const int STEP_SMEM = 56704 * 4;   // 226816 B
    cudaFuncSetAttribute(step_loop_kernel, cudaFuncAttributeMaxDynamicSharedMemorySize, STEP_SMEM);

    // launch 0: all converts in ONE kernel
    cvt_fused<<<20804, 256>>>(img, W_fc, W1, gru_k, fc1_w, fc2_w, W2);
    // launch 1: gather
    gather_kernel<<<6016, 256>>>(target, emb);
    // launches 2-4: batched GEMMs
    mma_gemm_hf<<<dim3(2, 64), 256, SMEM_SZ>>>(imgH, imgL, wfcH, b_fc,
                                               features, featH, featL, 8192, 256, 2048, 1, 0);
    mma_gemm_hf<<<dim3(4, 64), 256, SMEM_SZ>>>(featH, featL, w1H, b1,
                                               featw1, nullptr, nullptr, 8192, 512, 256, 0, 0);
    mma_gemm_hf<<<dim3(12, 47), 256, SMEM_SZ>>>(etH, etL, gk2H, gru_b,
                                                embmx, nullptr, nullptr, 6016, 1536, 256, 0, 0);
    // launch 5: persistent step loop  (ncu -s 5 -c 1 profiles THIS)
    step_loop_kernel<<<128, 256, STEP_SMEM>>>(V, bV, b2, gru_b);
    // launches 6-7: fc1, fc2
    mma_gemm_hf<<<dim3(4, 47), 256, SMEM_SZ>>>(stH, stL, f1wH, fc1_b,
                                               nullptr, f1oH, f1oL, 6016, 512, 512, 0, 0);
    mma_gemm_hf<<<dim3(40, 47), 256, SMEM_SZ>>>(f1oH, f1oL, f2wH, fc2_b,
                                                out, nullptr, nullptr, 6016, 5000, 512, 0, 1);
}